// round 1
// baseline (speedup 1.0000x reference)
#include <cuda_runtime.h>
#include <cuda_bf16.h>
#include <math.h>

// Problem constants
#define BB 2
#define NA 64
#define NL 256
#define NN 320          // N = NA + NL
#define DD 128
#define HH 8
#define HDD 16
#define LL 3
#define TT 50
#define NPAIR (BB*NN*NN)     // 204800

// ---------------- device scratch (no allocation allowed) ----------------
__device__ float g_pf[BB*NN*3];
__device__ float g_rp [BB*NN*NN*DD];   // rel_pos       [b][n][m][d]
__device__ float g_rpn[BB*NN*NN*DD];   // rel_pos_neg   [b][n][m][d]
__device__ float g_x  [BB*NN*DD];
__device__ float g_h  [BB*NN*DD];
__device__ float g_qkv[BB*NN*3*DD];
__device__ float g_ctx[BB*NN*DD];
__device__ float g_hid[BB*NN*4*DD];

// ---------------- pose features ----------------
__global__ void pf_kernel(const float* __restrict__ xpos,
                          const float* __restrict__ xang,
                          const float* __restrict__ lpos) {
    int i = blockIdx.x * 128 + threadIdx.x;
    if (i >= BB*NN) return;
    int b = i / NN, n = i % NN;
    float px, py, pa;
    if (n < NA) {
        int base = ((b*NA + n)*TT + 49) * 2;
        px = xpos[base]; py = xpos[base+1];
        pa = xang[(b*NA + n)*TT + 49];
    } else {
        int l = n - NA;
        int base = (b*NL + l) * 20 * 2;   // LP=20, point 0
        px = lpos[base]; py = lpos[base+1];
        float x1 = lpos[base+2], y1 = lpos[base+3];  // point 1
        pa = atan2f(y1 - py, x1 - px);
    }
    g_pf[i*3+0] = px; g_pf[i*3+1] = py; g_pf[i*3+2] = pa;
}

// ---------------- rel-pos MLP as register-blocked SGEMM ----------------
// out[p, 0:128] = relu(rel[p,0:4] @ W1 + b1) @ W2 + b2,  p = pair index
// Block: 128 pairs x 128 outputs, 256 threads, 8x8 microtile, BK=16.
__global__ __launch_bounds__(256) void relmlp_kernel(
    const float* __restrict__ pw1, const float* __restrict__ pb1,
    const float* __restrict__ pw2, const float* __restrict__ pb2,
    const float* __restrict__ nw1, const float* __restrict__ nb1,
    const float* __restrict__ nw2, const float* __restrict__ nb2)
{
    const bool neg = (blockIdx.y != 0);
    const float* W1 = neg ? nw1 : pw1;
    const float* B1 = neg ? nb1 : pb1;
    const float* W2 = neg ? nw2 : pw2;
    const float* B2 = neg ? nb2 : pb2;
    float* out = neg ? g_rpn : g_rp;

    __shared__ float w1_s[4][128];
    __shared__ float b1_s[128], b2_s[128];
    __shared__ float rel_s[128][4];
    __shared__ float hid_s[128][17];       // [m][k], padded
    __shared__ float4 w2_s[16][32];        // [k][c/4]  (16 x 128 floats)

    int tid = threadIdx.x;
    if (tid < 128) {
        b1_s[tid] = B1[tid];
        b2_s[tid] = B2[tid];
        w1_s[0][tid] = W1[tid];
        w1_s[1][tid] = W1[128+tid];
        w1_s[2][tid] = W1[256+tid];
        w1_s[3][tid] = W1[384+tid];
        int p = blockIdx.x * 128 + tid;
        int b = p / (NN*NN);
        int r = p - b*(NN*NN);
        int n = r / NN;
        int m = r - n*NN;
        const float* pn = g_pf + (b*NN + n)*3;
        const float* pm = g_pf + (b*NN + m)*3;
        float dx = pn[0]-pm[0], dy = pn[1]-pm[1];
        float dist = sqrtf(dx*dx + dy*dy);
        float ad = pn[2]-pm[2];
        float sg = neg ? -1.f : 1.f;
        rel_s[tid][0] = sg*dx; rel_s[tid][1] = sg*dy;
        rel_s[tid][2] = dist;  rel_s[tid][3] = sg*ad;
    }
    __syncthreads();

    float acc[8][8];
    #pragma unroll
    for (int r = 0; r < 8; r++)
        #pragma unroll
        for (int c = 0; c < 8; c++) acc[r][c] = 0.f;

    int tx = tid & 15, ty = tid >> 4;

    for (int kt = 0; kt < 8; kt++) {
        // hidden tile: hid_s[m][k] for kk = kt*16+k
        for (int idx = tid; idx < 2048; idx += 256) {
            int m = idx >> 4, k = idx & 15;
            int kk = kt*16 + k;
            float h = b1_s[kk]
                + rel_s[m][0]*w1_s[0][kk] + rel_s[m][1]*w1_s[1][kk]
                + rel_s[m][2]*w1_s[2][kk] + rel_s[m][3]*w1_s[3][kk];
            hid_s[m][k] = fmaxf(h, 0.f);
        }
        // W2 tile
        const float4* W24 = reinterpret_cast<const float4*>(W2);
        for (int idx = tid; idx < 512; idx += 256) {
            int k = idx >> 5, c = idx & 31;
            w2_s[k][c] = W24[(kt*16 + k)*32 + c];
        }
        __syncthreads();
        #pragma unroll
        for (int k = 0; k < 16; k++) {
            float a[8];
            #pragma unroll
            for (int r = 0; r < 8; r++) a[r] = hid_s[ty*8 + r][k];
            float4 w0 = w2_s[k][tx*2], w1v = w2_s[k][tx*2 + 1];
            float w[8] = {w0.x, w0.y, w0.z, w0.w, w1v.x, w1v.y, w1v.z, w1v.w};
            #pragma unroll
            for (int r = 0; r < 8; r++)
                #pragma unroll
                for (int c = 0; c < 8; c++) acc[r][c] += a[r]*w[c];
        }
        __syncthreads();
    }

    int pbase = blockIdx.x * 128;
    #pragma unroll
    for (int r = 0; r < 8; r++) {
        int p = pbase + ty*8 + r;
        float4 v0, v1;
        v0.x = acc[r][0] + b2_s[tx*8+0];
        v0.y = acc[r][1] + b2_s[tx*8+1];
        v0.z = acc[r][2] + b2_s[tx*8+2];
        v0.w = acc[r][3] + b2_s[tx*8+3];
        v1.x = acc[r][4] + b2_s[tx*8+4];
        v1.y = acc[r][5] + b2_s[tx*8+5];
        v1.z = acc[r][6] + b2_s[tx*8+6];
        v1.w = acc[r][7] + b2_s[tx*8+7];
        float4* o = reinterpret_cast<float4*>(out + (size_t)p*128 + tx*8);
        o[0] = v0; o[1] = v1;
    }
}

// ---------------- init x = concat(agent, lane) ----------------
__global__ void initx_kernel(const float* __restrict__ agent,
                             const float* __restrict__ lane) {
    int i = blockIdx.x * 256 + threadIdx.x;
    if (i >= BB*NN*DD) return;
    int d = i & 127;
    int bn = i >> 7;
    int b = bn / NN, n = bn % NN;
    g_x[i] = (n < NA) ? agent[(b*NA + n)*DD + d]
                      : lane [(b*NL + (n - NA))*DD + d];
}

// ---------------- layernorm ----------------
__global__ void ln_kernel(const float* __restrict__ x,
                          const float* __restrict__ g,
                          const float* __restrict__ bta,
                          float* __restrict__ out) {
    int row = blockIdx.x, t = threadIdx.x;  // 128 threads
    float v = x[row*128 + t];
    __shared__ float sm[4];
    float s = v;
    #pragma unroll
    for (int o = 16; o; o >>= 1) s += __shfl_xor_sync(~0u, s, o);
    if ((t & 31) == 0) sm[t >> 5] = s;
    __syncthreads();
    float mu = (sm[0] + sm[1] + sm[2] + sm[3]) * 0.0078125f;
    float d = v - mu;
    float s2 = d*d;
    #pragma unroll
    for (int o = 16; o; o >>= 1) s2 += __shfl_xor_sync(~0u, s2, o);
    __syncthreads();
    if ((t & 31) == 0) sm[t >> 5] = s2;
    __syncthreads();
    float var = (sm[0] + sm[1] + sm[2] + sm[3]) * 0.0078125f;
    out[row*128 + t] = d * rsqrtf(var + 1e-5f) * g[t] + bta[t];
}

// ---------------- generic tiled GEMM: C = op(A@W + bias [+res]) ----------------
// BM=64, BN=64, BK=16, 128 threads, 8x4 per thread.
template<bool RELU, bool RES>
__global__ __launch_bounds__(128) void gemm64(
    const float* __restrict__ A, const float* __restrict__ W,
    const float* __restrict__ bias, const float* __restrict__ res,
    float* __restrict__ C, int M, int N, int K)
{
    __shared__ float As[16][65];
    __shared__ float Ws[16][64];
    int tid = threadIdx.x;
    int tx = tid & 15, ty = tid >> 4;
    int m0 = blockIdx.y * 64, n0 = blockIdx.x * 64;
    float acc[8][4];
    #pragma unroll
    for (int r = 0; r < 8; r++)
        #pragma unroll
        for (int c = 0; c < 4; c++) acc[r][c] = 0.f;

    for (int k0 = 0; k0 < K; k0 += 16) {
        for (int idx = tid; idx < 1024; idx += 128) {
            int m = idx >> 4, k = idx & 15;
            As[k][m] = A[(size_t)(m0 + m)*K + k0 + k];
        }
        for (int idx = tid; idx < 1024; idx += 128) {
            int k = idx >> 6, c = idx & 63;
            Ws[k][c] = W[(size_t)(k0 + k)*N + n0 + c];
        }
        __syncthreads();
        #pragma unroll
        for (int k = 0; k < 16; k++) {
            float a[8], w[4];
            #pragma unroll
            for (int r = 0; r < 8; r++) a[r] = As[k][ty*8 + r];
            #pragma unroll
            for (int c = 0; c < 4; c++) w[c] = Ws[k][tx*4 + c];
            #pragma unroll
            for (int r = 0; r < 8; r++)
                #pragma unroll
                for (int c = 0; c < 4; c++) acc[r][c] += a[r]*w[c];
        }
        __syncthreads();
    }
    #pragma unroll
    for (int r = 0; r < 8; r++) {
        int m = m0 + ty*8 + r;
        #pragma unroll
        for (int c = 0; c < 4; c++) {
            int n = n0 + tx*4 + c;
            float v = acc[r][c] + bias[n];
            if (RES)  v += res[(size_t)m*N + n];
            if (RELU) v = fmaxf(v, 0.f);
            C[(size_t)m*N + n] = v;
        }
    }
}

// ---------------- fused attention per (b, n) ----------------
// scores[h][m] = 0.25 * sum_d q[h,d]*(k[m,h,d] + rp[n,m,h,d]); mask; softmax
// ctx[h,d]   = sum_m a[h][m]*(v[m,h,d] + rpn[n,m,h,d])
__global__ __launch_bounds__(256) void attn_kernel(
    const unsigned char* __restrict__ xmask,
    const unsigned char* __restrict__ lmask)
{
    int bn = blockIdx.x;
    int b = bn / NN;
    int tid = threadIdx.x;

    __shared__ float q_s[128];
    __shared__ float s_s[8*NN];
    __shared__ float kb[8][132];
    __shared__ float rb[8][132];
    __shared__ float ctxp[2][128];

    if (tid < 128) q_s[tid] = g_qkv[(size_t)bn*384 + tid];
    __syncthreads();

    // ---- scores ----
    for (int mc = 0; mc < NN; mc += 8) {
        for (int idx = tid; idx < 1024; idx += 256) {
            int j = idx >> 7, c = idx & 127;
            kb[j][c] = g_qkv[(size_t)(b*NN + mc + j)*384 + 128 + c];
            rb[j][c] = g_rp [((size_t)bn*NN + mc + j)*128 + c];
        }
        __syncthreads();
        if (tid < 64) {
            int ml = tid >> 3, h = tid & 7;
            int m = mc + ml;
            float s = 0.f;
            #pragma unroll
            for (int d = 0; d < 16; d++) {
                float qv = q_s[h*16 + d];
                s += qv * (kb[ml][h*16 + d] + rb[ml][h*16 + d]);
            }
            s *= 0.25f;
            bool pm = (m < NA) ? (xmask[b*NA + m] != 0) : (lmask[b*NL + m - NA] != 0);
            if (pm) s = -1e9f;
            s_s[h*NN + m] = s;
        }
        __syncthreads();
    }

    // ---- softmax: one warp per head ----
    {
        int h = tid >> 5, lane = tid & 31;
        float mx = -1e30f;
        for (int m = lane; m < NN; m += 32) mx = fmaxf(mx, s_s[h*NN + m]);
        #pragma unroll
        for (int o = 16; o; o >>= 1) mx = fmaxf(mx, __shfl_xor_sync(~0u, mx, o));
        float sum = 0.f;
        for (int m = lane; m < NN; m += 32) {
            float e = __expf(s_s[h*NN + m] - mx);
            s_s[h*NN + m] = e;
            sum += e;
        }
        #pragma unroll
        for (int o = 16; o; o >>= 1) sum += __shfl_xor_sync(~0u, sum, o);
        float inv = 1.f / sum;
        for (int m = lane; m < NN; m += 32) s_s[h*NN + m] *= inv;
    }
    __syncthreads();

    // ---- context ----
    {
        int half = tid >> 7, t = tid & 127, h = t >> 4;
        float acc = 0.f;
        for (int m = half; m < NN; m += 2) {
            float a = s_s[h*NN + m];
            float v = g_qkv[(size_t)(b*NN + m)*384 + 256 + t];
            float r = g_rpn[((size_t)bn*NN + m)*128 + t];
            acc += a * (v + r);
        }
        ctxp[half][t] = acc;
    }
    __syncthreads();
    if (tid < 128)
        g_ctx[(size_t)bn*128 + tid] = ctxp[0][tid] + ctxp[1][tid];
}

// ---------------- launch ----------------
extern "C" void kernel_launch(void* const* d_in, const int* in_sizes, int n_in,
                              void* d_out, int out_size) {
    const float* agent = (const float*)d_in[0];
    const float* lane  = (const float*)d_in[1];
    const float* xpos  = (const float*)d_in[2];
    const float* xang  = (const float*)d_in[3];
    const float* lpos  = (const float*)d_in[4];
    const unsigned char* xmask = (const unsigned char*)d_in[5];
    const unsigned char* lmask = (const unsigned char*)d_in[6];
    const float* pw1 = (const float*)d_in[7];
    const float* pb1 = (const float*)d_in[8];
    const float* pw2 = (const float*)d_in[9];
    const float* pb2 = (const float*)d_in[10];
    const float* nw1 = (const float*)d_in[11];
    const float* nb1 = (const float*)d_in[12];
    const float* nw2 = (const float*)d_in[13];
    const float* nb2 = (const float*)d_in[14];
    const float* qkvw = (const float*)d_in[15];
    const float* qkvb = (const float*)d_in[16];
    const float* projw = (const float*)d_in[17];
    const float* projb = (const float*)d_in[18];
    const float* ln1g = (const float*)d_in[19];
    const float* ln1b = (const float*)d_in[20];
    const float* fc1w = (const float*)d_in[21];
    const float* fc1b = (const float*)d_in[22];
    const float* fc2w = (const float*)d_in[23];
    const float* fc2b = (const float*)d_in[24];
    const float* ln2g = (const float*)d_in[25];
    const float* ln2b = (const float*)d_in[26];

    float *px, *ph, *pqkv, *pctx, *phid;
    cudaGetSymbolAddress((void**)&px,   g_x);
    cudaGetSymbolAddress((void**)&ph,   g_h);
    cudaGetSymbolAddress((void**)&pqkv, g_qkv);
    cudaGetSymbolAddress((void**)&pctx, g_ctx);
    cudaGetSymbolAddress((void**)&phid, g_hid);

    pf_kernel<<<(BB*NN + 127)/128, 128>>>(xpos, xang, lpos);
    relmlp_kernel<<<dim3(NPAIR/128, 2), 256>>>(pw1, pb1, pw2, pb2,
                                               nw1, nb1, nw2, nb2);
    initx_kernel<<<(BB*NN*DD + 255)/256, 256>>>(agent, lane);

    const int M = BB*NN;  // 640
    for (int i = 0; i < LL; i++) {
        ln_kernel<<<M, 128>>>(px, ln1g + i*DD, ln1b + i*DD, ph);
        gemm64<false,false><<<dim3(6, M/64), 128>>>(
            ph, qkvw + (size_t)i*DD*3*DD, qkvb + i*3*DD, nullptr, pqkv,
            M, 3*DD, DD);
        attn_kernel<<<BB*NN, 256>>>(xmask, lmask);
        gemm64<false,true><<<dim3(2, M/64), 128>>>(
            pctx, projw + (size_t)i*DD*DD, projb + i*DD, px, px,
            M, DD, DD);
        ln_kernel<<<M, 128>>>(px, ln2g + i*DD, ln2b + i*DD, ph);
        gemm64<true,false><<<dim3(8, M/64), 128>>>(
            ph, fc1w + (size_t)i*DD*4*DD, fc1b + i*4*DD, nullptr, phid,
            M, 4*DD, DD);
        float* outx = (i == LL-1) ? (float*)d_out : px;
        gemm64<false,true><<<dim3(2, M/64), 128>>>(
            phid, fc2w + (size_t)i*4*DD*DD, fc2b + i*DD, px, outx,
            M, DD, 4*DD);
    }
}

// round 2
// speedup vs baseline: 1.2357x; 1.2357x over previous
#include <cuda_runtime.h>
#include <cuda_bf16.h>
#include <math.h>

// Problem constants
#define BB 2
#define NA 64
#define NL 256
#define NN 320          // N = NA + NL
#define DD 128
#define HH 8
#define HDD 16
#define LL 3
#define TT 50
#define NPAIR (BB*NN*NN)     // 204800

// ---------------- device scratch (no allocation allowed) ----------------
__device__ float g_pf[BB*NN*3];
__device__ float g_rp [BB*NN*NN*DD];   // rel_pos       [b][n][m][d]
__device__ float g_rpn[BB*NN*NN*DD];   // rel_pos_neg   [b][n][m][d]
__device__ float g_x  [BB*NN*DD];
__device__ float g_h  [BB*NN*DD];
__device__ float g_qkv[BB*NN*3*DD];
__device__ float g_ctx[BB*NN*DD];
__device__ float g_hid[BB*NN*4*DD];

// ---------------- pose features ----------------
__global__ void pf_kernel(const float* __restrict__ xpos,
                          const float* __restrict__ xang,
                          const float* __restrict__ lpos) {
    int i = blockIdx.x * 128 + threadIdx.x;
    if (i >= BB*NN) return;
    int b = i / NN, n = i % NN;
    float px, py, pa;
    if (n < NA) {
        int base = ((b*NA + n)*TT + 49) * 2;
        px = xpos[base]; py = xpos[base+1];
        pa = xang[(b*NA + n)*TT + 49];
    } else {
        int l = n - NA;
        int base = (b*NL + l) * 20 * 2;   // LP=20, point 0
        px = lpos[base]; py = lpos[base+1];
        float x1 = lpos[base+2], y1 = lpos[base+3];  // point 1
        pa = atan2f(y1 - py, x1 - px);
    }
    g_pf[i*3+0] = px; g_pf[i*3+1] = py; g_pf[i*3+2] = pa;
}

// ---------------- tf32 helpers ----------------
__device__ __forceinline__ unsigned f2tf32(float x) {
    unsigned y;
    asm("cvt.rna.tf32.f32 %0, %1;" : "=r"(y) : "f"(x));
    return y;
}

__device__ __forceinline__ void mma_tf32(float& d0, float& d1, float& d2, float& d3,
                                         unsigned a0, unsigned a1, unsigned a2, unsigned a3,
                                         unsigned b0, unsigned b1) {
    asm volatile(
        "mma.sync.aligned.m16n8k8.row.col.f32.tf32.tf32.f32 "
        "{%0,%1,%2,%3}, {%4,%5,%6,%7}, {%8,%9}, {%0,%1,%2,%3};"
        : "+f"(d0), "+f"(d1), "+f"(d2), "+f"(d3)
        : "r"(a0), "r"(a1), "r"(a2), "r"(a3), "r"(b0), "r"(b1));
}

// ---------------- rel-pos MLP via tf32 tensor cores ----------------
// out[p, 0:128] = relu(rel[p,0:4] @ W1 + b1) @ W2 + b2,  p = pair index.
// Block: 128 pairs (M) x 128 outputs (N), K=128 hidden, 256 threads / 8 warps.
// Warp w owns rows 16w..16w+15, all 128 cols (16 n-tiles of m16n8k8).
__global__ __launch_bounds__(256) void relmlp_kernel(
    const float* __restrict__ pw1, const float* __restrict__ pb1,
    const float* __restrict__ pw2, const float* __restrict__ pb2,
    const float* __restrict__ nw1, const float* __restrict__ nb1,
    const float* __restrict__ nw2, const float* __restrict__ nb2)
{
    const bool neg = (blockIdx.y != 0);
    const float* W1 = neg ? nw1 : pw1;
    const float* B1 = neg ? nb1 : pb1;
    const float* W2 = neg ? nw2 : pw2;
    const float* B2 = neg ? nb2 : pb2;
    float* out = neg ? g_rpn : g_rp;

    __shared__ float w1_s[4][128];
    __shared__ float b1_s[128], b2_s[128];
    __shared__ float rel_s[128][4];
    __shared__ unsigned hid_s[128][20];   // tf32 bits, k-tile of 16, pad->20 (conflict-free frag loads)
    __shared__ unsigned w2_s[16][136];    // tf32 bits, [k][n], pad->136 (conflict-free frag loads)

    int tid = threadIdx.x;
    int warp = tid >> 5, lane = tid & 31;
    int r0 = lane >> 2, cq = lane & 3;

    if (tid < 128) {
        b1_s[tid] = B1[tid];
        b2_s[tid] = B2[tid];
        w1_s[0][tid] = W1[tid];
        w1_s[1][tid] = W1[128+tid];
        w1_s[2][tid] = W1[256+tid];
        w1_s[3][tid] = W1[384+tid];
        int p = blockIdx.x * 128 + tid;
        int b = p / (NN*NN);
        int r = p - b*(NN*NN);
        int n = r / NN;
        int m = r - n*NN;
        const float* pn = g_pf + (b*NN + n)*3;
        const float* pm = g_pf + (b*NN + m)*3;
        float dx = pn[0]-pm[0], dy = pn[1]-pm[1];
        float dist = sqrtf(dx*dx + dy*dy);
        float ad = pn[2]-pm[2];
        float sg = neg ? -1.f : 1.f;
        rel_s[tid][0] = sg*dx; rel_s[tid][1] = sg*dy;
        rel_s[tid][2] = dist;  rel_s[tid][3] = sg*ad;
    }
    __syncthreads();

    float acc[16][4];
    #pragma unroll
    for (int nt = 0; nt < 16; nt++)
        #pragma unroll
        for (int c = 0; c < 4; c++) acc[nt][c] = 0.f;

    for (int kt = 0; kt < 8; kt++) {
        // hidden tile: hid_s[m][k], kk = kt*16+k, tf32-rounded
        for (int idx = tid; idx < 2048; idx += 256) {
            int m = idx >> 4, k = idx & 15;
            int kk = kt*16 + k;
            float h = b1_s[kk]
                + rel_s[m][0]*w1_s[0][kk] + rel_s[m][1]*w1_s[1][kk]
                + rel_s[m][2]*w1_s[2][kk] + rel_s[m][3]*w1_s[3][kk];
            hid_s[m][k] = f2tf32(fmaxf(h, 0.f));
        }
        // W2 tile [16 k][128 n], tf32-rounded
        for (int idx = tid; idx < 2048; idx += 256) {
            int k = idx >> 7, c = idx & 127;
            w2_s[k][c] = f2tf32(W2[(size_t)(kt*16 + k)*128 + c]);
        }
        __syncthreads();

        // A-fragments for both k-steps (k = 0..7 and 8..15 of this tile)
        int mb = warp * 16;
        unsigned a0 = hid_s[mb + r0    ][cq];
        unsigned a1 = hid_s[mb + r0 + 8][cq];
        unsigned a2 = hid_s[mb + r0    ][cq + 4];
        unsigned a3 = hid_s[mb + r0 + 8][cq + 4];
        unsigned a4 = hid_s[mb + r0    ][cq + 8];
        unsigned a5 = hid_s[mb + r0 + 8][cq + 8];
        unsigned a6 = hid_s[mb + r0    ][cq + 12];
        unsigned a7 = hid_s[mb + r0 + 8][cq + 12];

        #pragma unroll
        for (int nt = 0; nt < 16; nt++) {
            int nc = nt*8 + r0;
            unsigned b0 = w2_s[cq     ][nc];
            unsigned b1 = w2_s[cq + 4 ][nc];
            unsigned b2v= w2_s[cq + 8 ][nc];
            unsigned b3 = w2_s[cq + 12][nc];
            mma_tf32(acc[nt][0], acc[nt][1], acc[nt][2], acc[nt][3],
                     a0, a1, a2, a3, b0, b1);
            mma_tf32(acc[nt][0], acc[nt][1], acc[nt][2], acc[nt][3],
                     a4, a5, a6, a7, b2v, b3);
        }
        __syncthreads();
    }

    // epilogue: C frag (r0, cq*2), (r0, cq*2+1), (r0+8, cq*2), (r0+8, cq*2+1)
    int pbase = blockIdx.x * 128 + warp*16;
    #pragma unroll
    for (int nt = 0; nt < 16; nt++) {
        int col = nt*8 + cq*2;
        float bia0 = b2_s[col], bia1 = b2_s[col+1];
        float2 v0 = make_float2(acc[nt][0] + bia0, acc[nt][1] + bia1);
        float2 v1 = make_float2(acc[nt][2] + bia0, acc[nt][3] + bia1);
        *reinterpret_cast<float2*>(out + (size_t)(pbase + r0    )*128 + col) = v0;
        *reinterpret_cast<float2*>(out + (size_t)(pbase + r0 + 8)*128 + col) = v1;
    }
}

// ---------------- init x = concat(agent, lane) ----------------
__global__ void initx_kernel(const float* __restrict__ agent,
                             const float* __restrict__ lane) {
    int i = blockIdx.x * 256 + threadIdx.x;
    if (i >= BB*NN*DD) return;
    int d = i & 127;
    int bn = i >> 7;
    int b = bn / NN, n = bn % NN;
    g_x[i] = (n < NA) ? agent[(b*NA + n)*DD + d]
                      : lane [(b*NL + (n - NA))*DD + d];
}

// ---------------- layernorm ----------------
__global__ void ln_kernel(const float* __restrict__ x,
                          const float* __restrict__ g,
                          const float* __restrict__ bta,
                          float* __restrict__ out) {
    int row = blockIdx.x, t = threadIdx.x;  // 128 threads
    float v = x[row*128 + t];
    __shared__ float sm[4];
    float s = v;
    #pragma unroll
    for (int o = 16; o; o >>= 1) s += __shfl_xor_sync(~0u, s, o);
    if ((t & 31) == 0) sm[t >> 5] = s;
    __syncthreads();
    float mu = (sm[0] + sm[1] + sm[2] + sm[3]) * 0.0078125f;
    float d = v - mu;
    float s2 = d*d;
    #pragma unroll
    for (int o = 16; o; o >>= 1) s2 += __shfl_xor_sync(~0u, s2, o);
    __syncthreads();
    if ((t & 31) == 0) sm[t >> 5] = s2;
    __syncthreads();
    float var = (sm[0] + sm[1] + sm[2] + sm[3]) * 0.0078125f;
    out[row*128 + t] = d * rsqrtf(var + 1e-5f) * g[t] + bta[t];
}

// ---------------- generic tiled GEMM: C = op(A@W + bias [+res]) ----------------
// BM=32, BN=64, BK=16, 128 threads, 4x4 per thread (more blocks -> better wave fill).
template<bool RELU, bool RES>
__global__ __launch_bounds__(128) void gemm32(
    const float* __restrict__ A, const float* __restrict__ W,
    const float* __restrict__ bias, const float* __restrict__ res,
    float* __restrict__ C, int M, int N, int K)
{
    __shared__ float As[16][33];
    __shared__ float Ws[16][64];
    int tid = threadIdx.x;
    int tx = tid & 15, ty = tid >> 4;
    int m0 = blockIdx.y * 32, n0 = blockIdx.x * 64;
    float acc[4][4];
    #pragma unroll
    for (int r = 0; r < 4; r++)
        #pragma unroll
        for (int c = 0; c < 4; c++) acc[r][c] = 0.f;

    for (int k0 = 0; k0 < K; k0 += 16) {
        for (int idx = tid; idx < 512; idx += 128) {
            int m = idx >> 4, k = idx & 15;
            As[k][m] = A[(size_t)(m0 + m)*K + k0 + k];
        }
        for (int idx = tid; idx < 1024; idx += 128) {
            int k = idx >> 6, c = idx & 63;
            Ws[k][c] = W[(size_t)(k0 + k)*N + n0 + c];
        }
        __syncthreads();
        #pragma unroll
        for (int k = 0; k < 16; k++) {
            float a[4], w[4];
            #pragma unroll
            for (int r = 0; r < 4; r++) a[r] = As[k][ty*4 + r];
            #pragma unroll
            for (int c = 0; c < 4; c++) w[c] = Ws[k][tx*4 + c];
            #pragma unroll
            for (int r = 0; r < 4; r++)
                #pragma unroll
                for (int c = 0; c < 4; c++) acc[r][c] += a[r]*w[c];
        }
        __syncthreads();
    }
    #pragma unroll
    for (int r = 0; r < 4; r++) {
        int m = m0 + ty*4 + r;
        #pragma unroll
        for (int c = 0; c < 4; c++) {
            int n = n0 + tx*4 + c;
            float v = acc[r][c] + bias[n];
            if (RES)  v += res[(size_t)m*N + n];
            if (RELU) v = fmaxf(v, 0.f);
            C[(size_t)m*N + n] = v;
        }
    }
}

// ---------------- fused attention per (b, n) ----------------
// scores[h][m] = 0.25 * sum_d q[h,d]*(k[m,h,d] + rp[n,m,h,d]); mask; softmax
// ctx[h,d]   = sum_m a[h][m]*(v[m,h,d] + rpn[n,m,h,d])
__global__ __launch_bounds__(256) void attn_kernel(
    const unsigned char* __restrict__ xmask,
    const unsigned char* __restrict__ lmask)
{
    int bn = blockIdx.x;
    int b = bn / NN;
    int tid = threadIdx.x;

    __shared__ float q_s[128];
    __shared__ float s_s[8*NN];
    __shared__ float kb[32][132];
    __shared__ float rb[32][132];
    __shared__ float ctxp[2][128];

    if (tid < 128) q_s[tid] = g_qkv[(size_t)bn*384 + tid];
    __syncthreads();

    // ---- scores: chunks of 32 rows, all 256 threads (32 m x 8 h) ----
    for (int mc = 0; mc < NN; mc += 32) {
        for (int idx = tid; idx < 4096; idx += 256) {
            int j = idx >> 7, c = idx & 127;
            kb[j][c] = g_qkv[(size_t)(b*NN + mc + j)*384 + 128 + c];
            rb[j][c] = g_rp [((size_t)bn*NN + mc + j)*128 + c];
        }
        __syncthreads();
        {
            int ml = tid >> 3, h = tid & 7;
            int m = mc + ml;
            float s = 0.f;
            #pragma unroll
            for (int d = 0; d < 16; d++) {
                float qv = q_s[h*16 + d];
                s += qv * (kb[ml][h*16 + d] + rb[ml][h*16 + d]);
            }
            s *= 0.25f;
            bool pm = (m < NA) ? (xmask[b*NA + m] != 0) : (lmask[b*NL + m - NA] != 0);
            if (pm) s = -1e9f;
            s_s[h*NN + m] = s;
        }
        __syncthreads();
    }

    // ---- softmax: one warp per head ----
    {
        int h = tid >> 5, lane = tid & 31;
        float mx = -1e30f;
        for (int m = lane; m < NN; m += 32) mx = fmaxf(mx, s_s[h*NN + m]);
        #pragma unroll
        for (int o = 16; o; o >>= 1) mx = fmaxf(mx, __shfl_xor_sync(~0u, mx, o));
        float sum = 0.f;
        for (int m = lane; m < NN; m += 32) {
            float e = __expf(s_s[h*NN + m] - mx);
            s_s[h*NN + m] = e;
            sum += e;
        }
        #pragma unroll
        for (int o = 16; o; o >>= 1) sum += __shfl_xor_sync(~0u, sum, o);
        float inv = 1.f / sum;
        for (int m = lane; m < NN; m += 32) s_s[h*NN + m] *= inv;
    }
    __syncthreads();

    // ---- context ----
    {
        int half = tid >> 7, t = tid & 127, h = t >> 4;
        float acc = 0.f;
        for (int m = half; m < NN; m += 2) {
            float a = s_s[h*NN + m];
            float v = g_qkv[(size_t)(b*NN + m)*384 + 256 + t];
            float r = g_rpn[((size_t)bn*NN + m)*128 + t];
            acc += a * (v + r);
        }
        ctxp[half][t] = acc;
    }
    __syncthreads();
    if (tid < 128)
        g_ctx[(size_t)bn*128 + tid] = ctxp[0][tid] + ctxp[1][tid];
}

// ---------------- launch ----------------
extern "C" void kernel_launch(void* const* d_in, const int* in_sizes, int n_in,
                              void* d_out, int out_size) {
    const float* agent = (const float*)d_in[0];
    const float* lane  = (const float*)d_in[1];
    const float* xpos  = (const float*)d_in[2];
    const float* xang  = (const float*)d_in[3];
    const float* lpos  = (const float*)d_in[4];
    const unsigned char* xmask = (const unsigned char*)d_in[5];
    const unsigned char* lmask = (const unsigned char*)d_in[6];
    const float* pw1 = (const float*)d_in[7];
    const float* pb1 = (const float*)d_in[8];
    const float* pw2 = (const float*)d_in[9];
    const float* pb2 = (const float*)d_in[10];
    const float* nw1 = (const float*)d_in[11];
    const float* nb1 = (const float*)d_in[12];
    const float* nw2 = (const float*)d_in[13];
    const float* nb2 = (const float*)d_in[14];
    const float* qkvw = (const float*)d_in[15];
    const float* qkvb = (const float*)d_in[16];
    const float* projw = (const float*)d_in[17];
    const float* projb = (const float*)d_in[18];
    const float* ln1g = (const float*)d_in[19];
    const float* ln1b = (const float*)d_in[20];
    const float* fc1w = (const float*)d_in[21];
    const float* fc1b = (const float*)d_in[22];
    const float* fc2w = (const float*)d_in[23];
    const float* fc2b = (const float*)d_in[24];
    const float* ln2g = (const float*)d_in[25];
    const float* ln2b = (const float*)d_in[26];

    float *px, *ph, *pqkv, *pctx, *phid;
    cudaGetSymbolAddress((void**)&px,   g_x);
    cudaGetSymbolAddress((void**)&ph,   g_h);
    cudaGetSymbolAddress((void**)&pqkv, g_qkv);
    cudaGetSymbolAddress((void**)&pctx, g_ctx);
    cudaGetSymbolAddress((void**)&phid, g_hid);

    pf_kernel<<<(BB*NN + 127)/128, 128>>>(xpos, xang, lpos);
    relmlp_kernel<<<dim3(NPAIR/128, 2), 256>>>(pw1, pb1, pw2, pb2,
                                               nw1, nb1, nw2, nb2);
    initx_kernel<<<(BB*NN*DD + 255)/256, 256>>>(agent, lane);

    const int M = BB*NN;  // 640
    for (int i = 0; i < LL; i++) {
        ln_kernel<<<M, 128>>>(px, ln1g + i*DD, ln1b + i*DD, ph);
        gemm32<false,false><<<dim3(6, M/32), 128>>>(
            ph, qkvw + (size_t)i*DD*3*DD, qkvb + i*3*DD, nullptr, pqkv,
            M, 3*DD, DD);
        attn_kernel<<<BB*NN, 256>>>(xmask, lmask);
        gemm32<false,true><<<dim3(2, M/32), 128>>>(
            pctx, projw + (size_t)i*DD*DD, projb + i*DD, px, px,
            M, DD, DD);
        ln_kernel<<<M, 128>>>(px, ln2g + i*DD, ln2b + i*DD, ph);
        gemm32<true,false><<<dim3(8, M/32), 128>>>(
            ph, fc1w + (size_t)i*DD*4*DD, fc1b + i*4*DD, nullptr, phid,
            M, 4*DD, DD);
        float* outx = (i == LL-1) ? (float*)d_out : px;
        gemm32<false,true><<<dim3(2, M/32), 128>>>(
            phid, fc2w + (size_t)i*4*DD*DD, fc2b + i*DD, px, outx,
            M, DD, 4*DD);
    }
}

// round 3
// speedup vs baseline: 1.6765x; 1.3567x over previous
#include <cuda_runtime.h>
#include <cuda_bf16.h>
#include <cuda_fp16.h>
#include <math.h>

// Problem constants
#define BB 2
#define NA 64
#define NL 256
#define NN 320          // N = NA + NL
#define DD 128
#define HH 8
#define HDD 16
#define LL 3
#define TT 50
#define NPAIR (BB*NN*NN)     // 204800

// ---------------- device scratch ----------------
__device__ float g_pf[BB*NN*3];
__device__ __half g_rph [NPAIR*DD];   // rel_pos       [b][n][m][d] fp16
__device__ __half g_rpnh[NPAIR*DD];   // rel_pos_neg
__device__ __half g_w2t[2][DD*DD];    // W2 transposed [n][k], fp16 (0=pos,1=neg)
__device__ float g_x  [BB*NN*DD];
__device__ float g_qkv[BB*NN*3*DD];
__device__ float g_ctx[BB*NN*DD];
__device__ float g_hid[BB*NN*4*DD];

// ---------------- pose features ----------------
__global__ void pf_kernel(const float* __restrict__ xpos,
                          const float* __restrict__ xang,
                          const float* __restrict__ lpos) {
    int i = blockIdx.x * 128 + threadIdx.x;
    if (i >= BB*NN) return;
    int b = i / NN, n = i % NN;
    float px, py, pa;
    if (n < NA) {
        int base = ((b*NA + n)*TT + 49) * 2;
        px = xpos[base]; py = xpos[base+1];
        pa = xang[(b*NA + n)*TT + 49];
    } else {
        int l = n - NA;
        int base = (b*NL + l) * 20 * 2;   // LP=20, point 0
        px = lpos[base]; py = lpos[base+1];
        float x1 = lpos[base+2], y1 = lpos[base+3];
        pa = atan2f(y1 - py, x1 - px);
    }
    g_pf[i*3+0] = px; g_pf[i*3+1] = py; g_pf[i*3+2] = pa;
}

// ---------------- W2 -> fp16 transposed, once ----------------
__global__ void prep_w2_kernel(const float* __restrict__ pw2,
                               const float* __restrict__ nw2) {
    int idx = blockIdx.x * 512 + threadIdx.x;   // 2*128*128 = 32768
    if (idx >= 2*DD*DD) return;
    int s = idx >> 14;
    int r = idx & 16383;
    int n = r >> 7, k = r & 127;
    const float* W2 = s ? nw2 : pw2;
    g_w2t[s][n*DD + k] = __float2half(W2[k*DD + n]);
}

// ---------------- fp16 MMA helper ----------------
__device__ __forceinline__ void mma_f16(float& d0, float& d1, float& d2, float& d3,
                                        unsigned a0, unsigned a1, unsigned a2, unsigned a3,
                                        unsigned b0, unsigned b1) {
    asm volatile(
        "mma.sync.aligned.m16n8k16.row.col.f32.f16.f16.f32 "
        "{%0,%1,%2,%3}, {%4,%5,%6,%7}, {%8,%9}, {%0,%1,%2,%3};"
        : "+f"(d0), "+f"(d1), "+f"(d2), "+f"(d3)
        : "r"(a0), "r"(a1), "r"(a2), "r"(a3), "r"(b0), "r"(b1));
}

__device__ __forceinline__ unsigned pack2(float lo, float hi) {
    __half2 h = __floats2half2_rn(lo, hi);
    return *reinterpret_cast<unsigned*>(&h);
}

// ---------------- rel-pos MLP: hidden in registers + fp16 MMA ----------------
// Block: 128 pairs x 128 outputs, 512 threads / 16 warps.
// Warp w: row-group mg = w>>1 (16 rows), col-half nh = w&1 (64 cols, 8 n-tiles).
__global__ __launch_bounds__(512) void relmlp_kernel(
    const float* __restrict__ pw1, const float* __restrict__ pb1,
    const float* __restrict__ pb2,
    const float* __restrict__ nw1, const float* __restrict__ nb1,
    const float* __restrict__ nb2)
{
    const int sign = blockIdx.y;                 // 0 = pos, 1 = neg
    const float* W1 = sign ? nw1 : pw1;
    const float* B1 = sign ? nb1 : pb1;
    const float* B2 = sign ? nb2 : pb2;
    __half* out = sign ? g_rpnh : g_rph;

    __shared__ float w1_s[4][128];
    __shared__ float b1_s[128], b2_s[128];
    __shared__ float rel_s[128][4];
    __shared__ __half2 w2t_s[128][68];           // [n][kpair], padded

    int tid = threadIdx.x;
    int warp = tid >> 5, lane = tid & 31;
    int mg = warp >> 1, nh = warp & 1;
    int r0 = lane >> 2, cq = lane & 3;
    int mb = mg * 16;

    if (tid < 128) {
        b2_s[tid] = B2[tid];
        int p = blockIdx.x * 128 + tid;
        int b = p / (NN*NN);
        int r = p - b*(NN*NN);
        int n = r / NN;
        int m = r - n*NN;
        const float* pn = g_pf + (b*NN + n)*3;
        const float* pm = g_pf + (b*NN + m)*3;
        float dx = pn[0]-pm[0], dy = pn[1]-pm[1];
        float dist = sqrtf(dx*dx + dy*dy);
        float ad = pn[2]-pm[2];
        float sg = sign ? -1.f : 1.f;
        rel_s[tid][0] = sg*dx; rel_s[tid][1] = sg*dy;
        rel_s[tid][2] = dist;  rel_s[tid][3] = sg*ad;
    } else if (tid < 256) {
        int t = tid - 128;
        b1_s[t] = B1[t];
        w1_s[0][t] = W1[t];
        w1_s[1][t] = W1[128+t];
        w1_s[2][t] = W1[256+t];
        w1_s[3][t] = W1[384+t];
    }
    // W2^T fp16 tile (32KB): 2048 uint4
    {
        const uint4* src = reinterpret_cast<const uint4*>(&g_w2t[sign][0]);
        for (int idx = tid; idx < 2048; idx += 512) {
            int n = idx >> 4, c = idx & 15;
            *reinterpret_cast<uint4*>(&w2t_s[n][c*4]) = src[idx];
        }
    }
    __syncthreads();

    // hidden layer directly into A-fragment registers
    float ra0 = rel_s[mb+r0][0], ra1 = rel_s[mb+r0][1],
          ra2 = rel_s[mb+r0][2], ra3 = rel_s[mb+r0][3];
    float rb0 = rel_s[mb+r0+8][0], rb1 = rel_s[mb+r0+8][1],
          rb2 = rel_s[mb+r0+8][2], rb3 = rel_s[mb+r0+8][3];

    unsigned ha[8][4];
    #pragma unroll
    for (int s = 0; s < 8; s++) {
        #pragma unroll
        for (int pp = 0; pp < 2; pp++) {
            int k0 = s*16 + 2*cq + pp*8;
            float w0a = w1_s[0][k0],   w1a = w1_s[1][k0],
                  w2a = w1_s[2][k0],   w3a = w1_s[3][k0],   bba = b1_s[k0];
            float w0b = w1_s[0][k0+1], w1b = w1_s[1][k0+1],
                  w2b = w1_s[2][k0+1], w3b = w1_s[3][k0+1], bbb = b1_s[k0+1];
            float hA0 = fmaxf(bba + ra0*w0a + ra1*w1a + ra2*w2a + ra3*w3a, 0.f);
            float hA1 = fmaxf(bbb + ra0*w0b + ra1*w1b + ra2*w2b + ra3*w3b, 0.f);
            float hB0 = fmaxf(bba + rb0*w0a + rb1*w1a + rb2*w2a + rb3*w3a, 0.f);
            float hB1 = fmaxf(bbb + rb0*w0b + rb1*w1b + rb2*w2b + rb3*w3b, 0.f);
            ha[s][pp*2 + 0] = pack2(hA0, hA1);   // a0 / a2
            ha[s][pp*2 + 1] = pack2(hB0, hB1);   // a1 / a3
        }
    }

    float acc[8][4];
    #pragma unroll
    for (int nt = 0; nt < 8; nt++)
        #pragma unroll
        for (int c = 0; c < 4; c++) acc[nt][c] = 0.f;

    #pragma unroll
    for (int s = 0; s < 8; s++) {
        #pragma unroll
        for (int nt = 0; nt < 8; nt++) {
            int nc = nh*64 + nt*8 + r0;
            unsigned b0 = *reinterpret_cast<unsigned*>(&w2t_s[nc][8*s + cq]);
            unsigned b1 = *reinterpret_cast<unsigned*>(&w2t_s[nc][8*s + cq + 4]);
            mma_f16(acc[nt][0], acc[nt][1], acc[nt][2], acc[nt][3],
                    ha[s][0], ha[s][1], ha[s][2], ha[s][3], b0, b1);
        }
    }

    int pbase = blockIdx.x * 128 + mb;
    #pragma unroll
    for (int nt = 0; nt < 8; nt++) {
        int col = nh*64 + nt*8 + 2*cq;
        float bi0 = b2_s[col], bi1 = b2_s[col+1];
        __half2 v0 = __floats2half2_rn(acc[nt][0] + bi0, acc[nt][1] + bi1);
        __half2 v1 = __floats2half2_rn(acc[nt][2] + bi0, acc[nt][3] + bi1);
        *reinterpret_cast<__half2*>(out + (size_t)(pbase + r0    )*128 + col) = v0;
        *reinterpret_cast<__half2*>(out + (size_t)(pbase + r0 + 8)*128 + col) = v1;
    }
}

// ---------------- init x = concat(agent, lane) ----------------
__global__ void initx_kernel(const float* __restrict__ agent,
                             const float* __restrict__ lane) {
    int i = blockIdx.x * 256 + threadIdx.x;
    if (i >= BB*NN*DD) return;
    int d = i & 127;
    int bn = i >> 7;
    int b = bn / NN, n = bn % NN;
    g_x[i] = (n < NA) ? agent[(b*NA + n)*DD + d]
                      : lane [(b*NL + (n - NA))*DD + d];
}

// ---------------- fused LN + GEMM (K = 128): C = op(LN(A) @ W + bias) ----------------
// BM=32, BN=64, 128 threads.
template<bool RELU>
__global__ __launch_bounds__(128) void gemmln(
    const float* __restrict__ A, const float* __restrict__ W,
    const float* __restrict__ bias,
    const float* __restrict__ lng, const float* __restrict__ lnb,
    float* __restrict__ C, int M, int N)
{
    __shared__ float As[32][132];
    __shared__ float Ws[16][64];
    __shared__ float gs[128], bs[128];

    int tid = threadIdx.x;
    int tx = tid & 15, ty = tid >> 4;
    int m0 = blockIdx.y * 32, n0 = blockIdx.x * 64;

    if (tid < 128) { gs[tid] = lng[tid]; bs[tid] = lnb[tid]; }
    for (int idx = tid; idx < 4096; idx += 128) {
        int m = idx >> 7, k = idx & 127;
        As[m][k] = A[(size_t)(m0 + m)*128 + k];
    }
    __syncthreads();

    // LN: warp w handles rows w*8 .. w*8+7
    {
        int w = tid >> 5, lane = tid & 31;
        for (int r = 0; r < 8; r++) {
            int row = w*8 + r;
            float v0 = As[row][lane], v1 = As[row][lane+32],
                  v2 = As[row][lane+64], v3 = As[row][lane+96];
            float s = v0+v1+v2+v3;
            #pragma unroll
            for (int o = 16; o; o >>= 1) s += __shfl_xor_sync(~0u, s, o);
            float mu = s * 0.0078125f;
            float d0 = v0-mu, d1 = v1-mu, d2 = v2-mu, d3 = v3-mu;
            float q = d0*d0 + d1*d1 + d2*d2 + d3*d3;
            #pragma unroll
            for (int o = 16; o; o >>= 1) q += __shfl_xor_sync(~0u, q, o);
            float rs = rsqrtf(q * 0.0078125f + 1e-5f);
            As[row][lane   ] = d0*rs*gs[lane   ] + bs[lane   ];
            As[row][lane+32] = d1*rs*gs[lane+32] + bs[lane+32];
            As[row][lane+64] = d2*rs*gs[lane+64] + bs[lane+64];
            As[row][lane+96] = d3*rs*gs[lane+96] + bs[lane+96];
        }
    }
    __syncthreads();

    float acc[4][4];
    #pragma unroll
    for (int r = 0; r < 4; r++)
        #pragma unroll
        for (int c = 0; c < 4; c++) acc[r][c] = 0.f;

    for (int k0 = 0; k0 < 128; k0 += 16) {
        for (int idx = tid; idx < 1024; idx += 128) {
            int k = idx >> 6, c = idx & 63;
            Ws[k][c] = W[(size_t)(k0 + k)*N + n0 + c];
        }
        __syncthreads();
        #pragma unroll
        for (int k = 0; k < 16; k++) {
            float a[4], w[4];
            #pragma unroll
            for (int r = 0; r < 4; r++) a[r] = As[ty*4 + r][k0 + k];
            #pragma unroll
            for (int c = 0; c < 4; c++) w[c] = Ws[k][tx*4 + c];
            #pragma unroll
            for (int r = 0; r < 4; r++)
                #pragma unroll
                for (int c = 0; c < 4; c++) acc[r][c] += a[r]*w[c];
        }
        __syncthreads();
    }
    #pragma unroll
    for (int r = 0; r < 4; r++) {
        int m = m0 + ty*4 + r;
        #pragma unroll
        for (int c = 0; c < 4; c++) {
            int n = n0 + tx*4 + c;
            float v = acc[r][c] + bias[n];
            if (RELU) v = fmaxf(v, 0.f);
            C[(size_t)m*N + n] = v;
        }
    }
}

// ---------------- plain tiled GEMM: C = A@W + bias [+res] ----------------
template<bool RELU, bool RES>
__global__ __launch_bounds__(128) void gemm32(
    const float* __restrict__ A, const float* __restrict__ W,
    const float* __restrict__ bias, const float* __restrict__ res,
    float* __restrict__ C, int M, int N, int K)
{
    __shared__ float As[16][33];
    __shared__ float Ws[16][64];
    int tid = threadIdx.x;
    int tx = tid & 15, ty = tid >> 4;
    int m0 = blockIdx.y * 32, n0 = blockIdx.x * 64;
    float acc[4][4];
    #pragma unroll
    for (int r = 0; r < 4; r++)
        #pragma unroll
        for (int c = 0; c < 4; c++) acc[r][c] = 0.f;

    for (int k0 = 0; k0 < K; k0 += 16) {
        for (int idx = tid; idx < 512; idx += 128) {
            int m = idx >> 4, k = idx & 15;
            As[k][m] = A[(size_t)(m0 + m)*K + k0 + k];
        }
        for (int idx = tid; idx < 1024; idx += 128) {
            int k = idx >> 6, c = idx & 63;
            Ws[k][c] = W[(size_t)(k0 + k)*N + n0 + c];
        }
        __syncthreads();
        #pragma unroll
        for (int k = 0; k < 16; k++) {
            float a[4], w[4];
            #pragma unroll
            for (int r = 0; r < 4; r++) a[r] = As[k][ty*4 + r];
            #pragma unroll
            for (int c = 0; c < 4; c++) w[c] = Ws[k][tx*4 + c];
            #pragma unroll
            for (int r = 0; r < 4; r++)
                #pragma unroll
                for (int c = 0; c < 4; c++) acc[r][c] += a[r]*w[c];
        }
        __syncthreads();
    }
    #pragma unroll
    for (int r = 0; r < 4; r++) {
        int m = m0 + ty*4 + r;
        #pragma unroll
        for (int c = 0; c < 4; c++) {
            int n = n0 + tx*4 + c;
            float v = acc[r][c] + bias[n];
            if (RES)  v += res[(size_t)m*N + n];
            if (RELU) v = fmaxf(v, 0.f);
            C[(size_t)m*N + n] = v;
        }
    }
}

// ---------------- fused attention per (b, n) ----------------
__global__ __launch_bounds__(256) void attn_kernel(
    const unsigned char* __restrict__ xmask,
    const unsigned char* __restrict__ lmask)
{
    int bn = blockIdx.x;
    int b = bn / NN;
    int tid = threadIdx.x;

    __shared__ float q_s[128];
    __shared__ float s_s[8*NN];
    __shared__ float kb[32][132];
    __shared__ __half rb[32][136];
    __shared__ float ctxp[4][128];

    if (tid < 128) q_s[tid] = g_qkv[(size_t)bn*384 + tid];
    __syncthreads();

    // ---- scores: chunks of 32 rows ----
    for (int mc = 0; mc < NN; mc += 32) {
        for (int idx = tid; idx < 4096; idx += 256) {
            int j = idx >> 7, c = idx & 127;
            kb[j][c] = g_qkv[(size_t)(b*NN + mc + j)*384 + 128 + c];
        }
        // rp fp16: 32 rows x 128 halves = 512 uint4
        for (int idx = tid; idx < 512; idx += 256) {
            int j = idx >> 4, c = idx & 15;
            *reinterpret_cast<uint4*>(&rb[j][c*8]) =
                *reinterpret_cast<const uint4*>(
                    g_rph + ((size_t)bn*NN + mc + j)*128 + c*8);
        }
        __syncthreads();
        {
            int ml = tid >> 3, h = tid & 7;
            int m = mc + ml;
            float s = 0.f;
            #pragma unroll
            for (int d = 0; d < 16; d++) {
                float qv = q_s[h*16 + d];
                s += qv * (kb[ml][h*16 + d] + __half2float(rb[ml][h*16 + d]));
            }
            s *= 0.25f;
            bool pm = (m < NA) ? (xmask[b*NA + m] != 0) : (lmask[b*NL + m - NA] != 0);
            if (pm) s = -1e9f;
            s_s[h*NN + m] = s;
        }
        __syncthreads();
    }

    // ---- softmax: one warp per head ----
    {
        int h = tid >> 5, lane = tid & 31;
        float mx = -1e30f;
        for (int m = lane; m < NN; m += 32) mx = fmaxf(mx, s_s[h*NN + m]);
        #pragma unroll
        for (int o = 16; o; o >>= 1) mx = fmaxf(mx, __shfl_xor_sync(~0u, mx, o));
        float sum = 0.f;
        for (int m = lane; m < NN; m += 32) {
            float e = __expf(s_s[h*NN + m] - mx);
            s_s[h*NN + m] = e;
            sum += e;
        }
        #pragma unroll
        for (int o = 16; o; o >>= 1) sum += __shfl_xor_sync(~0u, sum, o);
        float inv = 1.f / sum;
        for (int m = lane; m < NN; m += 32) s_s[h*NN + m] *= inv;
    }
    __syncthreads();

    // ---- context: thread owns d-pair, 4 m-slices ----
    {
        int ms = tid >> 6, t2 = tid & 63;
        int h = t2 >> 3;
        float ax = 0.f, ay = 0.f;
        for (int m = ms; m < NN; m += 4) {
            float a = s_s[h*NN + m];
            float2 v = *reinterpret_cast<const float2*>(
                g_qkv + (size_t)(b*NN + m)*384 + 256 + t2*2);
            __half2 rh = *reinterpret_cast<const __half2*>(
                g_rpnh + ((size_t)bn*NN + m)*128 + t2*2);
            float2 rf = __half22float2(rh);
            ax += a * (v.x + rf.x);
            ay += a * (v.y + rf.y);
        }
        ctxp[ms][t2*2    ] = ax;
        ctxp[ms][t2*2 + 1] = ay;
    }
    __syncthreads();
    if (tid < 128)
        g_ctx[(size_t)bn*128 + tid] =
            ctxp[0][tid] + ctxp[1][tid] + ctxp[2][tid] + ctxp[3][tid];
}

// ---------------- launch ----------------
extern "C" void kernel_launch(void* const* d_in, const int* in_sizes, int n_in,
                              void* d_out, int out_size) {
    const float* agent = (const float*)d_in[0];
    const float* lane  = (const float*)d_in[1];
    const float* xpos  = (const float*)d_in[2];
    const float* xang  = (const float*)d_in[3];
    const float* lpos  = (const float*)d_in[4];
    const unsigned char* xmask = (const unsigned char*)d_in[5];
    const unsigned char* lmask = (const unsigned char*)d_in[6];
    const float* pw1 = (const float*)d_in[7];
    const float* pb1 = (const float*)d_in[8];
    const float* pw2 = (const float*)d_in[9];
    const float* pb2 = (const float*)d_in[10];
    const float* nw1 = (const float*)d_in[11];
    const float* nb1 = (const float*)d_in[12];
    const float* nw2 = (const float*)d_in[13];
    const float* nb2 = (const float*)d_in[14];
    const float* qkvw = (const float*)d_in[15];
    const float* qkvb = (const float*)d_in[16];
    const float* projw = (const float*)d_in[17];
    const float* projb = (const float*)d_in[18];
    const float* ln1g = (const float*)d_in[19];
    const float* ln1b = (const float*)d_in[20];
    const float* fc1w = (const float*)d_in[21];
    const float* fc1b = (const float*)d_in[22];
    const float* fc2w = (const float*)d_in[23];
    const float* fc2b = (const float*)d_in[24];
    const float* ln2g = (const float*)d_in[25];
    const float* ln2b = (const float*)d_in[26];

    float *px, *pqkv, *pctx, *phid;
    cudaGetSymbolAddress((void**)&px,   g_x);
    cudaGetSymbolAddress((void**)&pqkv, g_qkv);
    cudaGetSymbolAddress((void**)&pctx, g_ctx);
    cudaGetSymbolAddress((void**)&phid, g_hid);

    pf_kernel<<<(BB*NN + 127)/128, 128>>>(xpos, xang, lpos);
    prep_w2_kernel<<<64, 512>>>(pw2, nw2);
    relmlp_kernel<<<dim3(NPAIR/128, 2), 512>>>(pw1, pb1, pb2, nw1, nb1, nb2);
    initx_kernel<<<(BB*NN*DD + 255)/256, 256>>>(agent, lane);

    const int M = BB*NN;  // 640
    for (int i = 0; i < LL; i++) {
        gemmln<false><<<dim3(6, M/32), 128>>>(
            px, qkvw + (size_t)i*DD*3*DD, qkvb + i*3*DD,
            ln1g + i*DD, ln1b + i*DD, pqkv, M, 3*DD);
        attn_kernel<<<BB*NN, 256>>>(xmask, lmask);
        gemm32<false,true><<<dim3(2, M/32), 128>>>(
            pctx, projw + (size_t)i*DD*DD, projb + i*DD, px, px,
            M, DD, DD);
        gemmln<true><<<dim3(8, M/32), 128>>>(
            px, fc1w + (size_t)i*DD*4*DD, fc1b + i*4*DD,
            ln2g + i*DD, ln2b + i*DD, phid, M, 4*DD);
        float* outx = (i == LL-1) ? (float*)d_out : px;
        gemm32<false,true><<<dim3(2, M/32), 128>>>(
            phid, fc2w + (size_t)i*4*DD*DD, fc2b + i*DD, px, outx,
            M, DD, 4*DD);
    }
}

// round 4
// speedup vs baseline: 2.1840x; 1.3028x over previous
#include <cuda_runtime.h>
#include <cuda_bf16.h>
#include <cuda_fp16.h>
#include <math.h>

// Problem constants
#define BB 2
#define NA 64
#define NL 256
#define NN 320          // N = NA + NL
#define DD 128
#define HH 8
#define HDD 16
#define LL 3
#define TT 50
#define NPAIR (BB*NN*NN)     // 204800

// ---------------- device scratch ----------------
__device__ float g_pf[BB*NN*3];
__device__ __half g_rph [NPAIR*DD];   // rel_pos       [b][n][m][d] fp16
__device__ __half g_rpnh[NPAIR*DD];   // rel_pos_neg
__device__ __half g_w2t[2][DD*DD];    // W2 transposed [n][k], fp16 (0=pos,1=neg)
__device__ float g_x  [BB*NN*DD];
__device__ __half g_qh [BB*NN*DD];    // q fp16
__device__ __half g_kvh[BB*NN*256];   // k (0:128) | v (128:256) fp16
__device__ float g_hid[BB*NN*4*DD];

// ---------------- fused prep: pf + W2->fp16^T + initx, one launch ----------------
__global__ void prep_kernel(const float* __restrict__ xpos,
                            const float* __restrict__ xang,
                            const float* __restrict__ lpos,
                            const float* __restrict__ pw2,
                            const float* __restrict__ nw2,
                            const float* __restrict__ agent,
                            const float* __restrict__ lane) {
    int blk = blockIdx.x;
    int t = threadIdx.x;
    if (blk < 3) {                       // pose features: 640 items
        int i = blk * 256 + t;
        if (i >= BB*NN) return;
        int b = i / NN, n = i % NN;
        float px, py, pa;
        if (n < NA) {
            int base = ((b*NA + n)*TT + 49) * 2;
            px = xpos[base]; py = xpos[base+1];
            pa = xang[(b*NA + n)*TT + 49];
        } else {
            int l = n - NA;
            int base = (b*NL + l) * 20 * 2;
            px = lpos[base]; py = lpos[base+1];
            float x1 = lpos[base+2], y1 = lpos[base+3];
            pa = atan2f(y1 - py, x1 - px);
        }
        g_pf[i*3+0] = px; g_pf[i*3+1] = py; g_pf[i*3+2] = pa;
    } else if (blk < 3 + 128) {          // W2 transpose: 32768 items
        int idx = (blk - 3) * 256 + t;
        int s = idx >> 14;
        int r = idx & 16383;
        int n = r >> 7, k = r & 127;
        const float* W2 = s ? nw2 : pw2;
        g_w2t[s][n*DD + k] = __float2half(W2[k*DD + n]);
    } else {                             // initx: 81920 items
        int i = (blk - 131) * 256 + t;
        if (i >= BB*NN*DD) return;
        int d = i & 127;
        int bn = i >> 7;
        int b = bn / NN, n = bn % NN;
        g_x[i] = (n < NA) ? agent[(b*NA + n)*DD + d]
                          : lane [(b*NL + (n - NA))*DD + d];
    }
}

// ---------------- fp16 MMA helper ----------------
__device__ __forceinline__ void mma_f16(float& d0, float& d1, float& d2, float& d3,
                                        unsigned a0, unsigned a1, unsigned a2, unsigned a3,
                                        unsigned b0, unsigned b1) {
    asm volatile(
        "mma.sync.aligned.m16n8k16.row.col.f32.f16.f16.f32 "
        "{%0,%1,%2,%3}, {%4,%5,%6,%7}, {%8,%9}, {%0,%1,%2,%3};"
        : "+f"(d0), "+f"(d1), "+f"(d2), "+f"(d3)
        : "r"(a0), "r"(a1), "r"(a2), "r"(a3), "r"(b0), "r"(b1));
}

__device__ __forceinline__ unsigned pack2(float lo, float hi) {
    __half2 h = __floats2half2_rn(lo, hi);
    return *reinterpret_cast<unsigned*>(&h);
}

// ---------------- rel-pos MLP: hidden in registers + fp16 MMA ----------------
__global__ __launch_bounds__(512) void relmlp_kernel(
    const float* __restrict__ pw1, const float* __restrict__ pb1,
    const float* __restrict__ pb2,
    const float* __restrict__ nw1, const float* __restrict__ nb1,
    const float* __restrict__ nb2)
{
    const int sign = blockIdx.y;                 // 0 = pos, 1 = neg
    const float* W1 = sign ? nw1 : pw1;
    const float* B1 = sign ? nb1 : pb1;
    const float* B2 = sign ? nb2 : pb2;
    __half* out = sign ? g_rpnh : g_rph;

    __shared__ float w1_s[4][128];
    __shared__ float b1_s[128], b2_s[128];
    __shared__ float rel_s[128][4];
    __shared__ __half2 w2t_s[128][68];           // [n][kpair], padded

    int tid = threadIdx.x;
    int warp = tid >> 5, lane = tid & 31;
    int mg = warp >> 1, nh = warp & 1;
    int r0 = lane >> 2, cq = lane & 3;
    int mb = mg * 16;

    if (tid < 128) {
        b2_s[tid] = B2[tid];
        int p = blockIdx.x * 128 + tid;
        int b = p / (NN*NN);
        int r = p - b*(NN*NN);
        int n = r / NN;
        int m = r - n*NN;
        const float* pn = g_pf + (b*NN + n)*3;
        const float* pm = g_pf + (b*NN + m)*3;
        float dx = pn[0]-pm[0], dy = pn[1]-pm[1];
        float dist = sqrtf(dx*dx + dy*dy);
        float ad = pn[2]-pm[2];
        float sg = sign ? -1.f : 1.f;
        rel_s[tid][0] = sg*dx; rel_s[tid][1] = sg*dy;
        rel_s[tid][2] = dist;  rel_s[tid][3] = sg*ad;
    } else if (tid < 256) {
        int t = tid - 128;
        b1_s[t] = B1[t];
        w1_s[0][t] = W1[t];
        w1_s[1][t] = W1[128+t];
        w1_s[2][t] = W1[256+t];
        w1_s[3][t] = W1[384+t];
    }
    {
        const uint4* src = reinterpret_cast<const uint4*>(&g_w2t[sign][0]);
        for (int idx = tid; idx < 2048; idx += 512) {
            int n = idx >> 4, c = idx & 15;
            *reinterpret_cast<uint4*>(&w2t_s[n][c*4]) = src[idx];
        }
    }
    __syncthreads();

    float ra0 = rel_s[mb+r0][0], ra1 = rel_s[mb+r0][1],
          ra2 = rel_s[mb+r0][2], ra3 = rel_s[mb+r0][3];
    float rb0 = rel_s[mb+r0+8][0], rb1 = rel_s[mb+r0+8][1],
          rb2 = rel_s[mb+r0+8][2], rb3 = rel_s[mb+r0+8][3];

    unsigned ha[8][4];
    #pragma unroll
    for (int s = 0; s < 8; s++) {
        #pragma unroll
        for (int pp = 0; pp < 2; pp++) {
            int k0 = s*16 + 2*cq + pp*8;
            float w0a = w1_s[0][k0],   w1a = w1_s[1][k0],
                  w2a = w1_s[2][k0],   w3a = w1_s[3][k0],   bba = b1_s[k0];
            float w0b = w1_s[0][k0+1], w1b = w1_s[1][k0+1],
                  w2b = w1_s[2][k0+1], w3b = w1_s[3][k0+1], bbb = b1_s[k0+1];
            float hA0 = fmaxf(bba + ra0*w0a + ra1*w1a + ra2*w2a + ra3*w3a, 0.f);
            float hA1 = fmaxf(bbb + ra0*w0b + ra1*w1b + ra2*w2b + ra3*w3b, 0.f);
            float hB0 = fmaxf(bba + rb0*w0a + rb1*w1a + rb2*w2a + rb3*w3a, 0.f);
            float hB1 = fmaxf(bbb + rb0*w0b + rb1*w1b + rb2*w2b + rb3*w3b, 0.f);
            ha[s][pp*2 + 0] = pack2(hA0, hA1);
            ha[s][pp*2 + 1] = pack2(hB0, hB1);
        }
    }

    float acc[8][4];
    #pragma unroll
    for (int nt = 0; nt < 8; nt++)
        #pragma unroll
        for (int c = 0; c < 4; c++) acc[nt][c] = 0.f;

    #pragma unroll
    for (int s = 0; s < 8; s++) {
        #pragma unroll
        for (int nt = 0; nt < 8; nt++) {
            int nc = nh*64 + nt*8 + r0;
            unsigned b0 = *reinterpret_cast<unsigned*>(&w2t_s[nc][8*s + cq]);
            unsigned b1 = *reinterpret_cast<unsigned*>(&w2t_s[nc][8*s + cq + 4]);
            mma_f16(acc[nt][0], acc[nt][1], acc[nt][2], acc[nt][3],
                    ha[s][0], ha[s][1], ha[s][2], ha[s][3], b0, b1);
        }
    }

    int pbase = blockIdx.x * 128 + mb;
    #pragma unroll
    for (int nt = 0; nt < 8; nt++) {
        int col = nh*64 + nt*8 + 2*cq;
        float bi0 = b2_s[col], bi1 = b2_s[col+1];
        __half2 v0 = __floats2half2_rn(acc[nt][0] + bi0, acc[nt][1] + bi1);
        __half2 v1 = __floats2half2_rn(acc[nt][2] + bi0, acc[nt][3] + bi1);
        *reinterpret_cast<__half2*>(out + (size_t)(pbase + r0    )*128 + col) = v0;
        *reinterpret_cast<__half2*>(out + (size_t)(pbase + r0 + 8)*128 + col) = v1;
    }
}

// ---------------- fused LN + GEMM (K = 128) ----------------
// MODE: 0 = float out, 1 = relu float out, 2 = qkv -> fp16 split arrays
template<int MODE>
__global__ __launch_bounds__(128) void gemmln(
    const float* __restrict__ A, const float* __restrict__ W,
    const float* __restrict__ bias,
    const float* __restrict__ lng, const float* __restrict__ lnb,
    float* __restrict__ C, int M, int N)
{
    __shared__ float As[32][132];
    __shared__ float Ws[32][64];
    __shared__ float gs[128], bs[128];

    int tid = threadIdx.x;
    int tx = tid & 15, ty = tid >> 4;
    int m0 = blockIdx.y * 32, n0 = blockIdx.x * 64;

    if (tid < 128) { gs[tid] = lng[tid]; bs[tid] = lnb[tid]; }
    for (int idx = tid; idx < 4096; idx += 128) {
        int m = idx >> 7, k = idx & 127;
        As[m][k] = A[(size_t)(m0 + m)*128 + k];
    }
    __syncthreads();

    {
        int w = tid >> 5, lane = tid & 31;
        for (int r = 0; r < 8; r++) {
            int row = w*8 + r;
            float v0 = As[row][lane], v1 = As[row][lane+32],
                  v2 = As[row][lane+64], v3 = As[row][lane+96];
            float s = v0+v1+v2+v3;
            #pragma unroll
            for (int o = 16; o; o >>= 1) s += __shfl_xor_sync(~0u, s, o);
            float mu = s * 0.0078125f;
            float d0 = v0-mu, d1 = v1-mu, d2 = v2-mu, d3 = v3-mu;
            float q = d0*d0 + d1*d1 + d2*d2 + d3*d3;
            #pragma unroll
            for (int o = 16; o; o >>= 1) q += __shfl_xor_sync(~0u, q, o);
            float rs = rsqrtf(q * 0.0078125f + 1e-5f);
            As[row][lane   ] = d0*rs*gs[lane   ] + bs[lane   ];
            As[row][lane+32] = d1*rs*gs[lane+32] + bs[lane+32];
            As[row][lane+64] = d2*rs*gs[lane+64] + bs[lane+64];
            As[row][lane+96] = d3*rs*gs[lane+96] + bs[lane+96];
        }
    }
    __syncthreads();

    float acc[4][4];
    #pragma unroll
    for (int r = 0; r < 4; r++)
        #pragma unroll
        for (int c = 0; c < 4; c++) acc[r][c] = 0.f;

    for (int k0 = 0; k0 < 128; k0 += 32) {
        for (int idx = tid; idx < 2048; idx += 128) {
            int k = idx >> 6, c = idx & 63;
            Ws[k][c] = W[(size_t)(k0 + k)*N + n0 + c];
        }
        __syncthreads();
        #pragma unroll
        for (int k = 0; k < 32; k++) {
            float a[4], w[4];
            #pragma unroll
            for (int r = 0; r < 4; r++) a[r] = As[ty*4 + r][k0 + k];
            #pragma unroll
            for (int c = 0; c < 4; c++) w[c] = Ws[k][tx*4 + c];
            #pragma unroll
            for (int r = 0; r < 4; r++)
                #pragma unroll
                for (int c = 0; c < 4; c++) acc[r][c] += a[r]*w[c];
        }
        __syncthreads();
    }
    #pragma unroll
    for (int r = 0; r < 4; r++) {
        int m = m0 + ty*4 + r;
        #pragma unroll
        for (int c = 0; c < 4; c++) {
            int n = n0 + tx*4 + c;
            float v = acc[r][c] + bias[n];
            if (MODE == 1) v = fmaxf(v, 0.f);
            if (MODE == 2) {
                int seg = n >> 7, off = n & 127;
                if (seg == 0) g_qh [(size_t)m*128 + off]       = __float2half(v);
                else if (seg == 1) g_kvh[(size_t)m*256 + off]  = __float2half(v);
                else g_kvh[(size_t)m*256 + 128 + off]          = __float2half(v);
            } else {
                C[(size_t)m*N + n] = v;
            }
        }
    }
}

// ---------------- plain tiled GEMM: C = A@W + bias [+res], BK=32 ----------------
template<bool RELU, bool RES>
__global__ __launch_bounds__(128) void gemm32(
    const float* __restrict__ A, const float* __restrict__ W,
    const float* __restrict__ bias, const float* __restrict__ res,
    float* __restrict__ C, int M, int N, int K)
{
    __shared__ float As[32][33];
    __shared__ float Ws[32][64];
    int tid = threadIdx.x;
    int tx = tid & 15, ty = tid >> 4;
    int m0 = blockIdx.y * 32, n0 = blockIdx.x * 64;
    float acc[4][4];
    #pragma unroll
    for (int r = 0; r < 4; r++)
        #pragma unroll
        for (int c = 0; c < 4; c++) acc[r][c] = 0.f;

    for (int k0 = 0; k0 < K; k0 += 32) {
        for (int idx = tid; idx < 1024; idx += 128) {
            int m = idx >> 5, k = idx & 31;
            As[k][m] = A[(size_t)(m0 + m)*K + k0 + k];
        }
        for (int idx = tid; idx < 2048; idx += 128) {
            int k = idx >> 6, c = idx & 63;
            Ws[k][c] = W[(size_t)(k0 + k)*N + n0 + c];
        }
        __syncthreads();
        #pragma unroll
        for (int k = 0; k < 32; k++) {
            float a[4], w[4];
            #pragma unroll
            for (int r = 0; r < 4; r++) a[r] = As[k][ty*4 + r];
            #pragma unroll
            for (int c = 0; c < 4; c++) w[c] = Ws[k][tx*4 + c];
            #pragma unroll
            for (int r = 0; r < 4; r++)
                #pragma unroll
                for (int c = 0; c < 4; c++) acc[r][c] += a[r]*w[c];
        }
        __syncthreads();
    }
    #pragma unroll
    for (int r = 0; r < 4; r++) {
        int m = m0 + ty*4 + r;
        #pragma unroll
        for (int c = 0; c < 4; c++) {
            int n = n0 + tx*4 + c;
            float v = acc[r][c] + bias[n];
            if (RES)  v += res[(size_t)m*N + n];
            if (RELU) v = fmaxf(v, 0.f);
            C[(size_t)m*N + n] = v;
        }
    }
}

// ---------------- fused attention + proj + residual, per (b, n) ----------------
__global__ __launch_bounds__(256) void attn_kernel(
    const unsigned char* __restrict__ xmask,
    const unsigned char* __restrict__ lmask,
    const float* __restrict__ projw,
    const float* __restrict__ projb)
{
    int bn = blockIdx.x;
    int b = bn / NN;
    int tid = threadIdx.x;

    __shared__ __half q_s[128];
    __shared__ float s_s[8*NN];      // 10240 B
    __shared__ __half kb[64][136];   // 17408 B
    __shared__ __half rb[64][136];   // 17408 B
    __shared__ float ctxp[4][128];   // 2048 B
    __shared__ float ctx_s[128];     // 512 B

    if (tid < 16)
        reinterpret_cast<uint4*>(q_s)[tid] =
            reinterpret_cast<const uint4*>(g_qh + (size_t)bn*128)[tid];
    __syncthreads();

    // ---- scores: 5 chunks of 64 rows ----
    for (int mc = 0; mc < NN; mc += 64) {
        for (int idx = tid; idx < 1024; idx += 256) {
            int j = idx >> 4, c = (idx & 15)*8;
            *reinterpret_cast<uint4*>(&kb[j][c]) =
                *reinterpret_cast<const uint4*>(g_kvh + (size_t)(b*NN + mc + j)*256 + c);
            *reinterpret_cast<uint4*>(&rb[j][c]) =
                *reinterpret_cast<const uint4*>(g_rph + ((size_t)bn*NN + mc + j)*128 + c);
        }
        __syncthreads();
        #pragma unroll
        for (int rep = 0; rep < 2; rep++) {
            int ml = (tid >> 3) + rep*32;
            int h = tid & 7;
            int m = mc + ml;
            const __half2* q2 = reinterpret_cast<const __half2*>(&q_s[h*16]);
            const __half2* k2 = reinterpret_cast<const __half2*>(&kb[ml][h*16]);
            const __half2* r2 = reinterpret_cast<const __half2*>(&rb[ml][h*16]);
            float s = 0.f;
            #pragma unroll
            for (int j = 0; j < 8; j++) {
                float2 qf = __half22float2(q2[j]);
                float2 kf = __half22float2(k2[j]);
                float2 rf = __half22float2(r2[j]);
                s += qf.x*(kf.x + rf.x) + qf.y*(kf.y + rf.y);
            }
            s *= 0.25f;
            bool pm = (m < NA) ? (xmask[b*NA + m] != 0) : (lmask[b*NL + m - NA] != 0);
            if (pm) s = -1e9f;
            s_s[h*NN + m] = s;
        }
        __syncthreads();
    }

    // ---- softmax: one warp per head ----
    {
        int h = tid >> 5, lane = tid & 31;
        float mx = -1e30f;
        for (int m = lane; m < NN; m += 32) mx = fmaxf(mx, s_s[h*NN + m]);
        #pragma unroll
        for (int o = 16; o; o >>= 1) mx = fmaxf(mx, __shfl_xor_sync(~0u, mx, o));
        float sum = 0.f;
        for (int m = lane; m < NN; m += 32) {
            float e = __expf(s_s[h*NN + m] - mx);
            s_s[h*NN + m] = e;
            sum += e;
        }
        #pragma unroll
        for (int o = 16; o; o >>= 1) sum += __shfl_xor_sync(~0u, sum, o);
        float inv = 1.f / sum;
        for (int m = lane; m < NN; m += 32) s_s[h*NN + m] *= inv;
    }
    __syncthreads();

    // ---- context ----
    {
        int ms = tid >> 6, t2 = tid & 63;
        int h = t2 >> 3;
        float ax = 0.f, ay = 0.f;
        #pragma unroll 4
        for (int m = ms; m < NN; m += 4) {
            float a = s_s[h*NN + m];
            __half2 vh = *reinterpret_cast<const __half2*>(
                g_kvh + (size_t)(b*NN + m)*256 + 128 + t2*2);
            __half2 rh = *reinterpret_cast<const __half2*>(
                g_rpnh + ((size_t)bn*NN + m)*128 + t2*2);
            float2 vf = __half22float2(vh);
            float2 rf = __half22float2(rh);
            ax += a * (vf.x + rf.x);
            ay += a * (vf.y + rf.y);
        }
        ctxp[ms][t2*2    ] = ax;
        ctxp[ms][t2*2 + 1] = ay;
    }
    __syncthreads();
    if (tid < 128)
        ctx_s[tid] = ctxp[0][tid] + ctxp[1][tid] + ctxp[2][tid] + ctxp[3][tid];
    __syncthreads();

    // ---- proj + residual, in-place update of g_x row ----
    {
        int c = tid & 127, hf = tid >> 7;
        float acc = 0.f;
        #pragma unroll 8
        for (int d = hf*64; d < hf*64 + 64; d++)
            acc += ctx_s[d] * projw[(size_t)d*128 + c];
        ctxp[hf][c] = acc;
    }
    __syncthreads();
    if (tid < 128)
        g_x[(size_t)bn*128 + tid] += ctxp[0][tid] + ctxp[1][tid] + projb[tid];
}

// ---------------- launch ----------------
extern "C" void kernel_launch(void* const* d_in, const int* in_sizes, int n_in,
                              void* d_out, int out_size) {
    const float* agent = (const float*)d_in[0];
    const float* lane  = (const float*)d_in[1];
    const float* xpos  = (const float*)d_in[2];
    const float* xang  = (const float*)d_in[3];
    const float* lpos  = (const float*)d_in[4];
    const unsigned char* xmask = (const unsigned char*)d_in[5];
    const unsigned char* lmask = (const unsigned char*)d_in[6];
    const float* pw1 = (const float*)d_in[7];
    const float* pb1 = (const float*)d_in[8];
    const float* pw2 = (const float*)d_in[9];
    const float* pb2 = (const float*)d_in[10];
    const float* nw1 = (const float*)d_in[11];
    const float* nb1 = (const float*)d_in[12];
    const float* nw2 = (const float*)d_in[13];
    const float* nb2 = (const float*)d_in[14];
    const float* qkvw = (const float*)d_in[15];
    const float* qkvb = (const float*)d_in[16];
    const float* projw = (const float*)d_in[17];
    const float* projb = (const float*)d_in[18];
    const float* ln1g = (const float*)d_in[19];
    const float* ln1b = (const float*)d_in[20];
    const float* fc1w = (const float*)d_in[21];
    const float* fc1b = (const float*)d_in[22];
    const float* fc2w = (const float*)d_in[23];
    const float* fc2b = (const float*)d_in[24];
    const float* ln2g = (const float*)d_in[25];
    const float* ln2b = (const float*)d_in[26];

    float *px, *phid;
    cudaGetSymbolAddress((void**)&px,   g_x);
    cudaGetSymbolAddress((void**)&phid, g_hid);

    prep_kernel<<<3 + 128 + 320, 256>>>(xpos, xang, lpos, pw2, nw2, agent, lane);
    relmlp_kernel<<<dim3(NPAIR/128, 2), 512>>>(pw1, pb1, pb2, nw1, nb1, nb2);

    const int M = BB*NN;  // 640
    for (int i = 0; i < LL; i++) {
        gemmln<2><<<dim3(6, M/32), 128>>>(
            px, qkvw + (size_t)i*DD*3*DD, qkvb + i*3*DD,
            ln1g + i*DD, ln1b + i*DD, nullptr, M, 3*DD);
        attn_kernel<<<BB*NN, 256>>>(xmask, lmask,
                                    projw + (size_t)i*DD*DD, projb + i*DD);
        gemmln<1><<<dim3(8, M/32), 128>>>(
            px, fc1w + (size_t)i*DD*4*DD, fc1b + i*4*DD,
            ln2g + i*DD, ln2b + i*DD, phid, M, 4*DD);
        float* outx = (i == LL-1) ? (float*)d_out : px;
        gemm32<false,true><<<dim3(2, M/32), 128>>>(
            phid, fc2w + (size_t)i*4*DD*DD, fc2b + i*DD, px, outx,
            M, DD, 4*DD);
    }
}

// round 5
// speedup vs baseline: 2.3707x; 1.0855x over previous
#include <cuda_runtime.h>
#include <cuda_bf16.h>
#include <cuda_fp16.h>
#include <math.h>

// Problem constants
#define BB 2
#define NA 64
#define NL 256
#define NN 320          // N = NA + NL
#define DD 128
#define HH 8
#define HDD 16
#define LL 3
#define TT 50
#define NPAIR (BB*NN*NN)     // 204800
#define SP 321               // padded score stride (bank-conflict-free)

// ---------------- device scratch ----------------
__device__ float g_pf[BB*NN*3];
__device__ __half g_rph [NPAIR*DD];   // rel_pos       [b][n][m][d] fp16
__device__ __half g_rpnh[NPAIR*DD];   // rel_pos_neg
__device__ __half g_w2t[2][DD*DD];    // W2 transposed [n][k], fp16 (0=pos,1=neg)
__device__ float g_x  [BB*NN*DD];
__device__ __half g_qh [BB*NN*DD];    // q fp16
__device__ __half g_kvh[BB*NN*256];   // k (0:128) | v (128:256) fp16
__device__ float g_hid[BB*NN*4*DD];

// ---------------- fused prep: pf + W2->fp16^T + initx, one launch ----------------
__global__ void prep_kernel(const float* __restrict__ xpos,
                            const float* __restrict__ xang,
                            const float* __restrict__ lpos,
                            const float* __restrict__ pw2,
                            const float* __restrict__ nw2,
                            const float* __restrict__ agent,
                            const float* __restrict__ lane) {
    int blk = blockIdx.x;
    int t = threadIdx.x;
    if (blk < 3) {                       // pose features: 640 items
        int i = blk * 256 + t;
        if (i >= BB*NN) return;
        int b = i / NN, n = i % NN;
        float px, py, pa;
        if (n < NA) {
            int base = ((b*NA + n)*TT + 49) * 2;
            px = xpos[base]; py = xpos[base+1];
            pa = xang[(b*NA + n)*TT + 49];
        } else {
            int l = n - NA;
            int base = (b*NL + l) * 20 * 2;
            px = lpos[base]; py = lpos[base+1];
            float x1 = lpos[base+2], y1 = lpos[base+3];
            pa = atan2f(y1 - py, x1 - px);
        }
        g_pf[i*3+0] = px; g_pf[i*3+1] = py; g_pf[i*3+2] = pa;
    } else if (blk < 3 + 128) {          // W2 transpose: 32768 items
        int idx = (blk - 3) * 256 + t;
        int s = idx >> 14;
        int r = idx & 16383;
        int n = r >> 7, k = r & 127;
        const float* W2 = s ? nw2 : pw2;
        g_w2t[s][n*DD + k] = __float2half(W2[k*DD + n]);
    } else {                             // initx: 81920 items
        int i = (blk - 131) * 256 + t;
        if (i >= BB*NN*DD) return;
        int d = i & 127;
        int bn = i >> 7;
        int b = bn / NN, n = bn % NN;
        g_x[i] = (n < NA) ? agent[(b*NA + n)*DD + d]
                          : lane [(b*NL + (n - NA))*DD + d];
    }
}

// ---------------- fp16 MMA helper ----------------
__device__ __forceinline__ void mma_f16(float& d0, float& d1, float& d2, float& d3,
                                        unsigned a0, unsigned a1, unsigned a2, unsigned a3,
                                        unsigned b0, unsigned b1) {
    asm volatile(
        "mma.sync.aligned.m16n8k16.row.col.f32.f16.f16.f32 "
        "{%0,%1,%2,%3}, {%4,%5,%6,%7}, {%8,%9}, {%0,%1,%2,%3};"
        : "+f"(d0), "+f"(d1), "+f"(d2), "+f"(d3)
        : "r"(a0), "r"(a1), "r"(a2), "r"(a3), "r"(b0), "r"(b1));
}

__device__ __forceinline__ unsigned pack2(float lo, float hi) {
    __half2 h = __floats2half2_rn(lo, hi);
    return *reinterpret_cast<unsigned*>(&h);
}

// ---------------- rel-pos MLP: hidden in registers + fp16 MMA ----------------
__global__ __launch_bounds__(512) void relmlp_kernel(
    const float* __restrict__ pw1, const float* __restrict__ pb1,
    const float* __restrict__ pb2,
    const float* __restrict__ nw1, const float* __restrict__ nb1,
    const float* __restrict__ nb2)
{
    const int sign = blockIdx.y;                 // 0 = pos, 1 = neg
    const float* W1 = sign ? nw1 : pw1;
    const float* B1 = sign ? nb1 : pb1;
    const float* B2 = sign ? nb2 : pb2;
    __half* out = sign ? g_rpnh : g_rph;

    __shared__ float w1_s[4][128];
    __shared__ float b1_s[128], b2_s[128];
    __shared__ float rel_s[128][4];
    __shared__ __half2 w2t_s[128][68];           // [n][kpair], padded

    int tid = threadIdx.x;
    int warp = tid >> 5, lane = tid & 31;
    int mg = warp >> 1, nh = warp & 1;
    int r0 = lane >> 2, cq = lane & 3;
    int mb = mg * 16;

    if (tid < 128) {
        b2_s[tid] = B2[tid];
        int p = blockIdx.x * 128 + tid;
        int b = p / (NN*NN);
        int r = p - b*(NN*NN);
        int n = r / NN;
        int m = r - n*NN;
        const float* pn = g_pf + (b*NN + n)*3;
        const float* pm = g_pf + (b*NN + m)*3;
        float dx = pn[0]-pm[0], dy = pn[1]-pm[1];
        float dist = sqrtf(dx*dx + dy*dy);
        float ad = pn[2]-pm[2];
        float sg = sign ? -1.f : 1.f;
        rel_s[tid][0] = sg*dx; rel_s[tid][1] = sg*dy;
        rel_s[tid][2] = dist;  rel_s[tid][3] = sg*ad;
    } else if (tid < 256) {
        int t = tid - 128;
        b1_s[t] = B1[t];
        w1_s[0][t] = W1[t];
        w1_s[1][t] = W1[128+t];
        w1_s[2][t] = W1[256+t];
        w1_s[3][t] = W1[384+t];
    }
    {
        const uint4* src = reinterpret_cast<const uint4*>(&g_w2t[sign][0]);
        for (int idx = tid; idx < 2048; idx += 512) {
            int n = idx >> 4, c = idx & 15;
            *reinterpret_cast<uint4*>(&w2t_s[n][c*4]) = src[idx];
        }
    }
    __syncthreads();

    float ra0 = rel_s[mb+r0][0], ra1 = rel_s[mb+r0][1],
          ra2 = rel_s[mb+r0][2], ra3 = rel_s[mb+r0][3];
    float rb0 = rel_s[mb+r0+8][0], rb1 = rel_s[mb+r0+8][1],
          rb2 = rel_s[mb+r0+8][2], rb3 = rel_s[mb+r0+8][3];

    unsigned ha[8][4];
    #pragma unroll
    for (int s = 0; s < 8; s++) {
        #pragma unroll
        for (int pp = 0; pp < 2; pp++) {
            int k0 = s*16 + 2*cq + pp*8;
            float w0a = w1_s[0][k0],   w1a = w1_s[1][k0],
                  w2a = w1_s[2][k0],   w3a = w1_s[3][k0],   bba = b1_s[k0];
            float w0b = w1_s[0][k0+1], w1b = w1_s[1][k0+1],
                  w2b = w1_s[2][k0+1], w3b = w1_s[3][k0+1], bbb = b1_s[k0+1];
            float hA0 = fmaxf(bba + ra0*w0a + ra1*w1a + ra2*w2a + ra3*w3a, 0.f);
            float hA1 = fmaxf(bbb + ra0*w0b + ra1*w1b + ra2*w2b + ra3*w3b, 0.f);
            float hB0 = fmaxf(bba + rb0*w0a + rb1*w1a + rb2*w2a + rb3*w3a, 0.f);
            float hB1 = fmaxf(bbb + rb0*w0b + rb1*w1b + rb2*w2b + rb3*w3b, 0.f);
            ha[s][pp*2 + 0] = pack2(hA0, hA1);
            ha[s][pp*2 + 1] = pack2(hB0, hB1);
        }
    }

    float acc[8][4];
    #pragma unroll
    for (int nt = 0; nt < 8; nt++)
        #pragma unroll
        for (int c = 0; c < 4; c++) acc[nt][c] = 0.f;

    #pragma unroll
    for (int s = 0; s < 8; s++) {
        #pragma unroll
        for (int nt = 0; nt < 8; nt++) {
            int nc = nh*64 + nt*8 + r0;
            unsigned b0 = *reinterpret_cast<unsigned*>(&w2t_s[nc][8*s + cq]);
            unsigned b1 = *reinterpret_cast<unsigned*>(&w2t_s[nc][8*s + cq + 4]);
            mma_f16(acc[nt][0], acc[nt][1], acc[nt][2], acc[nt][3],
                    ha[s][0], ha[s][1], ha[s][2], ha[s][3], b0, b1);
        }
    }

    int pbase = blockIdx.x * 128 + mb;
    #pragma unroll
    for (int nt = 0; nt < 8; nt++) {
        int col = nh*64 + nt*8 + 2*cq;
        float bi0 = b2_s[col], bi1 = b2_s[col+1];
        __half2 v0 = __floats2half2_rn(acc[nt][0] + bi0, acc[nt][1] + bi1);
        __half2 v1 = __floats2half2_rn(acc[nt][2] + bi0, acc[nt][3] + bi1);
        *reinterpret_cast<__half2*>(out + (size_t)(pbase + r0    )*128 + col) = v0;
        *reinterpret_cast<__half2*>(out + (size_t)(pbase + r0 + 8)*128 + col) = v1;
    }
}

// ---------------- fused LN + GEMM (K = 128) ----------------
// MODE: 0 = float out, 1 = relu float out, 2 = qkv -> fp16 split arrays
template<int MODE>
__global__ __launch_bounds__(128) void gemmln(
    const float* __restrict__ A, const float* __restrict__ W,
    const float* __restrict__ bias,
    const float* __restrict__ lng, const float* __restrict__ lnb,
    float* __restrict__ C, int M, int N)
{
    __shared__ float As[32][132];
    __shared__ float Ws[32][64];
    __shared__ float gs[128], bs[128];

    int tid = threadIdx.x;
    int tx = tid & 15, ty = tid >> 4;
    int m0 = blockIdx.y * 32, n0 = blockIdx.x * 64;

    if (tid < 128) { gs[tid] = lng[tid]; bs[tid] = lnb[tid]; }
    for (int idx = tid; idx < 4096; idx += 128) {
        int m = idx >> 7, k = idx & 127;
        As[m][k] = A[(size_t)(m0 + m)*128 + k];
    }
    __syncthreads();

    {
        int w = tid >> 5, lane = tid & 31;
        for (int r = 0; r < 8; r++) {
            int row = w*8 + r;
            float v0 = As[row][lane], v1 = As[row][lane+32],
                  v2 = As[row][lane+64], v3 = As[row][lane+96];
            float s = v0+v1+v2+v3;
            #pragma unroll
            for (int o = 16; o; o >>= 1) s += __shfl_xor_sync(~0u, s, o);
            float mu = s * 0.0078125f;
            float d0 = v0-mu, d1 = v1-mu, d2 = v2-mu, d3 = v3-mu;
            float q = d0*d0 + d1*d1 + d2*d2 + d3*d3;
            #pragma unroll
            for (int o = 16; o; o >>= 1) q += __shfl_xor_sync(~0u, q, o);
            float rs = rsqrtf(q * 0.0078125f + 1e-5f);
            As[row][lane   ] = d0*rs*gs[lane   ] + bs[lane   ];
            As[row][lane+32] = d1*rs*gs[lane+32] + bs[lane+32];
            As[row][lane+64] = d2*rs*gs[lane+64] + bs[lane+64];
            As[row][lane+96] = d3*rs*gs[lane+96] + bs[lane+96];
        }
    }
    __syncthreads();

    float acc[4][4];
    #pragma unroll
    for (int r = 0; r < 4; r++)
        #pragma unroll
        for (int c = 0; c < 4; c++) acc[r][c] = 0.f;

    for (int k0 = 0; k0 < 128; k0 += 32) {
        for (int idx = tid; idx < 2048; idx += 128) {
            int k = idx >> 6, c = idx & 63;
            Ws[k][c] = W[(size_t)(k0 + k)*N + n0 + c];
        }
        __syncthreads();
        #pragma unroll
        for (int k = 0; k < 32; k++) {
            float a[4], w[4];
            #pragma unroll
            for (int r = 0; r < 4; r++) a[r] = As[ty*4 + r][k0 + k];
            #pragma unroll
            for (int c = 0; c < 4; c++) w[c] = Ws[k][tx*4 + c];
            #pragma unroll
            for (int r = 0; r < 4; r++)
                #pragma unroll
                for (int c = 0; c < 4; c++) acc[r][c] += a[r]*w[c];
        }
        __syncthreads();
    }
    #pragma unroll
    for (int r = 0; r < 4; r++) {
        int m = m0 + ty*4 + r;
        #pragma unroll
        for (int c = 0; c < 4; c++) {
            int n = n0 + tx*4 + c;
            float v = acc[r][c] + bias[n];
            if (MODE == 1) v = fmaxf(v, 0.f);
            if (MODE == 2) {
                int seg = n >> 7, off = n & 127;
                if (seg == 0) g_qh [(size_t)m*128 + off]       = __float2half(v);
                else if (seg == 1) g_kvh[(size_t)m*256 + off]  = __float2half(v);
                else g_kvh[(size_t)m*256 + 128 + off]          = __float2half(v);
            } else {
                C[(size_t)m*N + n] = v;
            }
        }
    }
}

// ---------------- plain tiled GEMM: C = A@W + bias [+res], BK=32 ----------------
template<bool RELU, bool RES>
__global__ __launch_bounds__(128) void gemm32(
    const float* __restrict__ A, const float* __restrict__ W,
    const float* __restrict__ bias, const float* __restrict__ res,
    float* __restrict__ C, int M, int N, int K)
{
    __shared__ float As[32][33];
    __shared__ float Ws[32][64];
    int tid = threadIdx.x;
    int tx = tid & 15, ty = tid >> 4;
    int m0 = blockIdx.y * 32, n0 = blockIdx.x * 64;
    float acc[4][4];
    #pragma unroll
    for (int r = 0; r < 4; r++)
        #pragma unroll
        for (int c = 0; c < 4; c++) acc[r][c] = 0.f;

    for (int k0 = 0; k0 < K; k0 += 32) {
        for (int idx = tid; idx < 1024; idx += 128) {
            int m = idx >> 5, k = idx & 31;
            As[k][m] = A[(size_t)(m0 + m)*K + k0 + k];
        }
        for (int idx = tid; idx < 2048; idx += 128) {
            int k = idx >> 6, c = idx & 63;
            Ws[k][c] = W[(size_t)(k0 + k)*N + n0 + c];
        }
        __syncthreads();
        #pragma unroll
        for (int k = 0; k < 32; k++) {
            float a[4], w[4];
            #pragma unroll
            for (int r = 0; r < 4; r++) a[r] = As[k][ty*4 + r];
            #pragma unroll
            for (int c = 0; c < 4; c++) w[c] = Ws[k][tx*4 + c];
            #pragma unroll
            for (int r = 0; r < 4; r++)
                #pragma unroll
                for (int c = 0; c < 4; c++) acc[r][c] += a[r]*w[c];
        }
        __syncthreads();
    }
    #pragma unroll
    for (int r = 0; r < 4; r++) {
        int m = m0 + ty*4 + r;
        #pragma unroll
        for (int c = 0; c < 4; c++) {
            int n = n0 + tx*4 + c;
            float v = acc[r][c] + bias[n];
            if (RES)  v += res[(size_t)m*N + n];
            if (RELU) v = fmaxf(v, 0.f);
            C[(size_t)m*N + n] = v;
        }
    }
}

// ---------------- fused attention + proj + residual, per (b, n) ----------------
// No smem staging: direct coalesced gmem reads of k/v/rp/rpn.
__global__ __launch_bounds__(256, 6) void attn_kernel(
    const unsigned char* __restrict__ xmask,
    const unsigned char* __restrict__ lmask,
    const float* __restrict__ projw,
    const float* __restrict__ projb)
{
    int bn = blockIdx.x;
    int b = bn / NN;
    int tid = threadIdx.x;

    __shared__ float s_s[8*SP];      // padded stride 321 -> conflict-free
    __shared__ float ctxp[8][128];   // ctx partials (also reused for proj)
    __shared__ float ctx_s[128];

    // ---- scores: thread (ml = tid>>3, h = tid&7), direct gmem ----
    {
        int ml = tid >> 3, h = tid & 7;
        const __half2* qg = reinterpret_cast<const __half2*>(
            g_qh + (size_t)bn*128 + h*16);
        __half2 q2[8];
        #pragma unroll
        for (int j = 0; j < 8; j++) q2[j] = qg[j];

        #pragma unroll 2
        for (int mc = 0; mc < NN; mc += 32) {
            int m = mc + ml;
            const __half2* k2 = reinterpret_cast<const __half2*>(
                g_kvh + (size_t)(b*NN + m)*256 + h*16);
            const __half2* r2 = reinterpret_cast<const __half2*>(
                g_rph + ((size_t)bn*NN + m)*128 + h*16);
            float s = 0.f;
            #pragma unroll
            for (int j = 0; j < 8; j++) {
                float2 qf = __half22float2(q2[j]);
                float2 kf = __half22float2(k2[j]);
                float2 rf = __half22float2(r2[j]);
                s += qf.x*(kf.x + rf.x) + qf.y*(kf.y + rf.y);
            }
            s *= 0.25f;
            bool pm = (m < NA) ? (xmask[b*NA + m] != 0)
                               : (lmask[b*NL + m - NA] != 0);
            if (pm) s = -1e9f;
            s_s[h*SP + m] = s;
        }
    }
    __syncthreads();

    // ---- softmax: one warp per head ----
    {
        int h = tid >> 5, lane = tid & 31;
        float mx = -1e30f;
        for (int m = lane; m < NN; m += 32) mx = fmaxf(mx, s_s[h*SP + m]);
        #pragma unroll
        for (int o = 16; o; o >>= 1) mx = fmaxf(mx, __shfl_xor_sync(~0u, mx, o));
        float sum = 0.f;
        for (int m = lane; m < NN; m += 32) {
            float e = __expf(s_s[h*SP + m] - mx);
            s_s[h*SP + m] = e;
            sum += e;
        }
        #pragma unroll
        for (int o = 16; o; o >>= 1) sum += __shfl_xor_sync(~0u, sum, o);
        float inv = 1.f / sum;
        for (int m = lane; m < NN; m += 32) s_s[h*SP + m] *= inv;
    }
    __syncthreads();

    // ---- context: thread (d4 = tid&31 -> 4 halves, ms = tid>>5), direct gmem ----
    {
        int d4 = tid & 31, ms = tid >> 5;
        int h = d4 >> 2;
        float a0 = 0.f, a1 = 0.f, a2 = 0.f, a3 = 0.f;
        #pragma unroll 4
        for (int m = ms; m < NN; m += 8) {
            float a = s_s[h*SP + m];
            const __half2* v2 = reinterpret_cast<const __half2*>(
                g_kvh + (size_t)(b*NN + m)*256 + 128 + d4*4);
            const __half2* r2 = reinterpret_cast<const __half2*>(
                g_rpnh + ((size_t)bn*NN + m)*128 + d4*4);
            __half2 va = v2[0], vb = v2[1];
            __half2 ra = r2[0], rb = r2[1];
            float2 vf = __half22float2(va), rf = __half22float2(ra);
            a0 += a*(vf.x + rf.x); a1 += a*(vf.y + rf.y);
            vf = __half22float2(vb); rf = __half22float2(rb);
            a2 += a*(vf.x + rf.x); a3 += a*(vf.y + rf.y);
        }
        ctxp[ms][d4*4 + 0] = a0;
        ctxp[ms][d4*4 + 1] = a1;
        ctxp[ms][d4*4 + 2] = a2;
        ctxp[ms][d4*4 + 3] = a3;
    }
    __syncthreads();
    if (tid < 128) {
        float s = 0.f;
        #pragma unroll
        for (int j = 0; j < 8; j++) s += ctxp[j][tid];
        ctx_s[tid] = s;
    }
    __syncthreads();

    // ---- proj + residual, in-place update of g_x row ----
    {
        int c = tid & 127, hf = tid >> 7;
        float acc = 0.f;
        #pragma unroll 8
        for (int d = hf*64; d < hf*64 + 64; d++)
            acc += ctx_s[d] * projw[(size_t)d*128 + c];
        ctxp[hf][c] = acc;
    }
    __syncthreads();
    if (tid < 128)
        g_x[(size_t)bn*128 + tid] += ctxp[0][tid] + ctxp[1][tid] + projb[tid];
}

// ---------------- launch ----------------
extern "C" void kernel_launch(void* const* d_in, const int* in_sizes, int n_in,
                              void* d_out, int out_size) {
    const float* agent = (const float*)d_in[0];
    const float* lane  = (const float*)d_in[1];
    const float* xpos  = (const float*)d_in[2];
    const float* xang  = (const float*)d_in[3];
    const float* lpos  = (const float*)d_in[4];
    const unsigned char* xmask = (const unsigned char*)d_in[5];
    const unsigned char* lmask = (const unsigned char*)d_in[6];
    const float* pw1 = (const float*)d_in[7];
    const float* pb1 = (const float*)d_in[8];
    const float* pw2 = (const float*)d_in[9];
    const float* pb2 = (const float*)d_in[10];
    const float* nw1 = (const float*)d_in[11];
    const float* nb1 = (const float*)d_in[12];
    const float* nw2 = (const float*)d_in[13];
    const float* nb2 = (const float*)d_in[14];
    const float* qkvw = (const float*)d_in[15];
    const float* qkvb = (const float*)d_in[16];
    const float* projw = (const float*)d_in[17];
    const float* projb = (const float*)d_in[18];
    const float* ln1g = (const float*)d_in[19];
    const float* ln1b = (const float*)d_in[20];
    const float* fc1w = (const float*)d_in[21];
    const float* fc1b = (const float*)d_in[22];
    const float* fc2w = (const float*)d_in[23];
    const float* fc2b = (const float*)d_in[24];
    const float* ln2g = (const float*)d_in[25];
    const float* ln2b = (const float*)d_in[26];

    float *px, *phid;
    cudaGetSymbolAddress((void**)&px,   g_x);
    cudaGetSymbolAddress((void**)&phid, g_hid);

    prep_kernel<<<3 + 128 + 320, 256>>>(xpos, xang, lpos, pw2, nw2, agent, lane);
    relmlp_kernel<<<dim3(NPAIR/128, 2), 512>>>(pw1, pb1, pb2, nw1, nb1, nb2);

    const int M = BB*NN;  // 640
    for (int i = 0; i < LL; i++) {
        gemmln<2><<<dim3(6, M/32), 128>>>(
            px, qkvw + (size_t)i*DD*3*DD, qkvb + i*3*DD,
            ln1g + i*DD, ln1b + i*DD, nullptr, M, 3*DD);
        attn_kernel<<<BB*NN, 256>>>(xmask, lmask,
                                    projw + (size_t)i*DD*DD, projb + i*DD);
        gemmln<1><<<dim3(8, M/32), 128>>>(
            px, fc1w + (size_t)i*DD*4*DD, fc1b + i*4*DD,
            ln2g + i*DD, ln2b + i*DD, phid, M, 4*DD);
        float* outx = (i == LL-1) ? (float*)d_out : px;
        gemm32<false,true><<<dim3(2, M/32), 128>>>(
            phid, fc2w + (size_t)i*4*DD*DD, fc2b + i*DD, px, outx,
            M, DD, 4*DD);
    }
}